// round 13
// baseline (speedup 1.0000x reference)
#include <cuda_runtime.h>
#include <math.h>

// Problem dims
#define C_   3
#define T_   100
#define B_   512
#define F_   128
#define HX_  128
#define HZ_  128
#define H_   256
#define EH_  128
#define L_   64

#define NB_   47   // CTAs per channel (47*11=517 >= 512; 141 CTAs, 1/SM)
#define RMAX_ 11   // rows per CTA

// packed fp32x2 FMA (sm_100+): d = a*b + c on two lanes
#define FMA2(d, a, b, c) \
    asm("fma.rn.f32x2 %0, %1, %2, %3;" : "=l"(d) : "l"(a), "l"(b), "l"(c))

// ---- big activations scratch ----
__device__ float g_PI[(size_t)C_ * T_ * B_ * H_];   // x@WxI + bihq2
__device__ float g_PO[(size_t)C_ * T_ * B_ * F_];   // x@WxO + bo3
__device__ float g_Hs[(size_t)C_ * T_ * B_ * H_];   // h at step input

// ---- folded weights (computed on-device each run; tiny) ----
__device__ float g_Weq[C_ * HX_ * L_];    // We_x @ Wqm              [128,64]/ch
__device__ float g_beq[C_ * L_];          // be@Wqm + bqm
__device__ float g_Wcomb[C_ * H_ * L_];   // We_h @ Wqm              [256,64]/ch
__device__ float g_Wihz[L_ * H_];         // Wzp @ Wih_z             [64,256]
__device__ float g_bihz[H_];              // bzp @ Wih_z
__device__ float g_Wdz[C_ * L_ * EH_];    // Wzp @ Wd_z              [64,128]/ch
__device__ float g_bdz[C_ * EH_];         // bzp@Wd_z + bd
__device__ float g_Wzo[C_ * L_ * F_];     // Wdz @ Wpm               [64,128]/ch
__device__ float g_Who[C_ * H_ * F_];     // Wd_h @ Wpm              [256,128]/ch
__device__ float g_bo[C_ * F_];           // bdz@Wpm + bpm
__device__ float g_Whh2[C_ * H_ * H_];    // Whh + Wcomb@Wihz        [256,256]/ch
__device__ float g_Whh2T[C_ * H_ * H_];   // transpose of Whh2       [256,256]/ch
__device__ float g_Wihq[C_ * HX_ * H_];   // Wih_x + Weq@Wihz        [128,256]/ch
__device__ float g_bihq[C_ * H_];         // bih+bhh+bihz + beq@Wihz
__device__ float g_Who2[C_ * H_ * F_];    // Who + Wcomb@Wzo         [256,128]/ch
__device__ float g_Wxo[C_ * HX_ * F_];    // Weq @ Wzo               [128,128]/ch
__device__ float g_bo2[C_ * F_];          // beq@Wzo + bo
__device__ float g_WxI[C_ * F_ * H_];     // Wx @ Wihq               [128,256]/ch
__device__ float g_bihq2[C_ * H_];        // bx@Wihq + bihq
__device__ float g_WxO[C_ * F_ * F_];     // Wx @ Wxo                [128,128]/ch
__device__ float g_bo3[C_ * F_];          // bx@Wxo + bo2

// ===========================================================================
// small GEMM block for weight folding: out[M,N] (ld ldo) = A[M,K]@Bm[K,N] (+addm)
// 4x4 register tile per thread; N multiple of 4; M%4 via scalar remainder.
// ===========================================================================
__device__ __forceinline__ void small_gemmK(const float* __restrict__ A, int lda,
                                            const float* __restrict__ Bm, int ldb,
                                            float* __restrict__ out, int ldo,
                                            int M, int N, int K,
                                            const float* __restrict__ addm,
                                            int ldam) {
    const int M4 = M >> 2;
    const int Nq = N >> 2;
    for (int idx = threadIdx.x; idx < M4 * Nq; idx += 256) {
        const int mg = idx / Nq, ng = idx % Nq;
        const int m = mg * 4, n = ng * 4;
        float4 s0, s1, s2, s3;
        if (addm) {
            s0 = *reinterpret_cast<const float4*>(addm + (size_t)(m + 0) * ldam + n);
            s1 = *reinterpret_cast<const float4*>(addm + (size_t)(m + 1) * ldam + n);
            s2 = *reinterpret_cast<const float4*>(addm + (size_t)(m + 2) * ldam + n);
            s3 = *reinterpret_cast<const float4*>(addm + (size_t)(m + 3) * ldam + n);
        } else {
            s0 = s1 = s2 = s3 = make_float4(0.f, 0.f, 0.f, 0.f);
        }
        const float* a0 = A + (size_t)(m + 0) * lda;
        const float* a1 = A + (size_t)(m + 1) * lda;
        const float* a2 = A + (size_t)(m + 2) * lda;
        const float* a3 = A + (size_t)(m + 3) * lda;
        const float* b = Bm + n;
#pragma unroll 4
        for (int k = 0; k < K; ++k) {
            const float4 bv = *reinterpret_cast<const float4*>(b + (size_t)k * ldb);
            const float v0 = a0[k], v1 = a1[k], v2 = a2[k], v3 = a3[k];
            s0.x = fmaf(v0, bv.x, s0.x); s0.y = fmaf(v0, bv.y, s0.y);
            s0.z = fmaf(v0, bv.z, s0.z); s0.w = fmaf(v0, bv.w, s0.w);
            s1.x = fmaf(v1, bv.x, s1.x); s1.y = fmaf(v1, bv.y, s1.y);
            s1.z = fmaf(v1, bv.z, s1.z); s1.w = fmaf(v1, bv.w, s1.w);
            s2.x = fmaf(v2, bv.x, s2.x); s2.y = fmaf(v2, bv.y, s2.y);
            s2.z = fmaf(v2, bv.z, s2.z); s2.w = fmaf(v2, bv.w, s2.w);
            s3.x = fmaf(v3, bv.x, s3.x); s3.y = fmaf(v3, bv.y, s3.y);
            s3.z = fmaf(v3, bv.z, s3.z); s3.w = fmaf(v3, bv.w, s3.w);
        }
        *reinterpret_cast<float4*>(out + (size_t)(m + 0) * ldo + n) = s0;
        *reinterpret_cast<float4*>(out + (size_t)(m + 1) * ldo + n) = s1;
        *reinterpret_cast<float4*>(out + (size_t)(m + 2) * ldo + n) = s2;
        *reinterpret_cast<float4*>(out + (size_t)(m + 3) * ldo + n) = s3;
    }
    // remainder rows (e.g. M==1 bias tasks)
    const int mrem0 = M4 * 4;
    for (int idx = threadIdx.x; idx < (M - mrem0) * N; idx += 256) {
        const int m = mrem0 + idx / N, n = idx % N;
        float s = addm ? addm[(size_t)m * ldam + n] : 0.f;
        const float* a = A + (size_t)m * lda;
        const float* b = Bm + n;
#pragma unroll 4
        for (int k = 0; k < K; ++k) s = fmaf(a[k], b[(size_t)k * ldb], s);
        out[(size_t)m * ldo + n] = s;
    }
}

// fold stage 1 (35 CTAs, 64x64 blocks)
__global__ void __launch_bounds__(256) kernelF1(
    const float* __restrict__ We, const float* __restrict__ be,
    const float* __restrict__ Wqm, const float* __restrict__ bqm,
    const float* __restrict__ Wzp, const float* __restrict__ bzp,
    const float* __restrict__ Wd, const float* __restrict__ bd,
    const float* __restrict__ Wih) {
    const int t = blockIdx.x;
    if (t < 6) {                       // Weq = We_x@Wqm   [128,64] (2 mblk)
        const int c = t >> 1, mb = t & 1;
        small_gemmK(We + (size_t)c * 384 * EH_ + mb * 64 * EH_, EH_,
                    Wqm + (size_t)c * EH_ * L_, L_,
                    g_Weq + c * HX_ * L_ + mb * 64 * L_, L_, 64, L_, EH_,
                    nullptr, 0);
    } else if (t < 18) {               // Wcomb = We_h@Wqm [256,64] (4 mblk)
        const int u = t - 6, c = u >> 2, mb = u & 3;
        small_gemmK(We + (size_t)c * 384 * EH_ + (128 + mb * 64) * EH_, EH_,
                    Wqm + (size_t)c * EH_ * L_, L_,
                    g_Wcomb + c * H_ * L_ + mb * 64 * L_, L_, 64, L_, EH_,
                    nullptr, 0);
    } else if (t < 24) {               // Wdz = Wzp@Wd_z [64,128] (2 nblk)
        const int u = t - 18, c = u >> 1, nb = u & 1;
        small_gemmK(Wzp, HZ_, Wd + (size_t)c * 384 * EH_ + nb * 64, EH_,
                    g_Wdz + c * L_ * EH_ + nb * 64, EH_, L_, 64, HZ_,
                    nullptr, 0);
    } else if (t < 28) {               // Wihz = Wzp@Wih_z [64,256] (4 nblk)
        const int nb = t - 24;
        small_gemmK(Wzp, HZ_, Wih + 128 * H_ + nb * 64, H_,
                    g_Wihz + nb * 64, H_, L_, 64, HZ_, nullptr, 0);
    } else if (t < 31) {               // beq = be@Wqm + bqm
        const int c = t - 28;
        small_gemmK(be + c * EH_, EH_, Wqm + (size_t)c * EH_ * L_, L_,
                    g_beq + c * L_, L_, 1, L_, EH_, bqm + c * L_, 0);
    } else if (t < 34) {               // bdz = bzp@Wd_z + bd
        const int c = t - 31;
        small_gemmK(bzp, HZ_, Wd + (size_t)c * 384 * EH_, EH_,
                    g_bdz + c * EH_, EH_, 1, EH_, HZ_, bd + c * EH_, 0);
    } else {                           // bihz = bzp@Wih_z
        small_gemmK(bzp, HZ_, Wih + 128 * H_, H_, g_bihz, H_, 1, H_, HZ_,
                    nullptr, 0);
    }
}

// fold stage 2 (108 CTAs, 64x64 blocks)
__global__ void __launch_bounds__(256) kernelF2(
    const float* __restrict__ Wd, const float* __restrict__ Wpm,
    const float* __restrict__ bpm, const float* __restrict__ Whh,
    const float* __restrict__ Wih, const float* __restrict__ bih,
    const float* __restrict__ bhh) {
    const int t = blockIdx.x;
    if (t < 6) {                       // Wzo = Wdz@Wpm [64,128] (2 nblk)
        const int c = t >> 1, nb = t & 1;
        small_gemmK(g_Wdz + c * L_ * EH_, EH_,
                    Wpm + (size_t)c * EH_ * F_ + nb * 64, F_,
                    g_Wzo + c * L_ * F_ + nb * 64, F_, L_, 64, EH_, nullptr, 0);
    } else if (t < 30) {               // Who = Wd_h@Wpm [256,128] (4m x 2n)
        const int u = t - 6, c = u >> 3, r = u & 7, mb = r >> 1, nb = r & 1;
        small_gemmK(Wd + (size_t)c * 384 * EH_ + (128 + mb * 64) * EH_, EH_,
                    Wpm + (size_t)c * EH_ * F_ + nb * 64, F_,
                    g_Who + c * H_ * F_ + mb * 64 * F_ + nb * 64, F_,
                    64, 64, EH_, nullptr, 0);
    } else if (t < 33) {               // bo = bdz@Wpm + bpm
        const int c = t - 30;
        small_gemmK(g_bdz + c * EH_, EH_, Wpm + (size_t)c * EH_ * F_, F_,
                    g_bo + c * F_, F_, 1, F_, EH_, bpm + c * F_, 0);
    } else if (t < 81) {               // Whh2 = Whh + Wcomb@Wihz (4m x 4n, K=64)
        const int u = t - 33, c = u >> 4, r = u & 15, mb = r >> 2, nb = r & 3;
        small_gemmK(g_Wcomb + c * H_ * L_ + mb * 64 * L_, L_,
                    g_Wihz + nb * 64, H_,
                    g_Whh2 + (size_t)c * H_ * H_ + mb * 64 * H_ + nb * 64, H_,
                    64, 64, L_, Whh + (size_t)mb * 64 * H_ + nb * 64, H_);
    } else if (t < 105) {              // Wihq = Wih_x + Weq@Wihz (2m x 4n, K=64)
        const int u = t - 81, c = u >> 3, r = u & 7, mb = r >> 2, nb = r & 3;
        small_gemmK(g_Weq + c * HX_ * L_ + mb * 64 * L_, L_,
                    g_Wihz + nb * 64, H_,
                    g_Wihq + (size_t)c * HX_ * H_ + mb * 64 * H_ + nb * 64, H_,
                    64, 64, L_, Wih + (size_t)mb * 64 * H_ + nb * 64, H_);
    } else {                           // bihq = bih+bhh+bihz + beq@Wihz
        const int c = t - 105;
        for (int n = threadIdx.x; n < H_; n += 256) {
            float s = bih[n] + bhh[n] + g_bihz[n];
            for (int l = 0; l < L_; ++l)
                s = fmaf(g_beq[c * L_ + l], g_Wihz[l * H_ + n], s);
            g_bihq[c * H_ + n] = s;
        }
    }
}

// fold stage 3 (51 CTAs)
__global__ void __launch_bounds__(256) kernelF3() {
    const int t = blockIdx.x;
    if (t < 24) {                      // Who2 = Who + Wcomb@Wzo (4m x 2n, K=64)
        const int c = t >> 3, r = t & 7, mb = r >> 1, nb = r & 1;
        small_gemmK(g_Wcomb + c * H_ * L_ + mb * 64 * L_, L_,
                    g_Wzo + c * L_ * F_ + nb * 64, F_,
                    g_Who2 + c * H_ * F_ + mb * 64 * F_ + nb * 64, F_,
                    64, 64, L_,
                    g_Who + c * H_ * F_ + mb * 64 * F_ + nb * 64, F_);
    } else if (t < 36) {               // Wxo = Weq@Wzo (2m x 2n, K=64)
        const int u = t - 24, c = u >> 2, r = u & 3, mb = r >> 1, nb = r & 1;
        small_gemmK(g_Weq + c * HX_ * L_ + mb * 64 * L_, L_,
                    g_Wzo + c * L_ * F_ + nb * 64, F_,
                    g_Wxo + c * HX_ * F_ + mb * 64 * F_ + nb * 64, F_,
                    64, 64, L_, nullptr, 0);
    } else if (t < 39) {               // bo2 = beq@Wzo + bo
        const int c = t - 36;
        small_gemmK(g_beq + c * L_, L_, g_Wzo + c * L_ * F_, F_,
                    g_bo2 + c * F_, F_, 1, F_, L_, g_bo + c * F_, 0);
    } else {                           // Whh2T = transpose(Whh2) (12 CTAs)
        const int u = t - 39, c = u >> 2, nb = u & 3;
        const float* src = g_Whh2 + (size_t)c * H_ * H_;
        float* dst = g_Whh2T + (size_t)c * H_ * H_;
        for (int idx = threadIdx.x; idx < 64 * H_; idx += 256) {
            const int n = nb * 64 + (idx >> 8);
            const int m = idx & 255;
            dst[(size_t)n * H_ + m] = src[(size_t)m * H_ + n];
        }
    }
}

// fold stage 4 (39 CTAs)
__global__ void __launch_bounds__(256) kernelF4(
    const float* __restrict__ Wx, const float* __restrict__ bx) {
    const int t = blockIdx.x;
    if (t < 24) {                      // WxI = Wx@Wihq (2m x 4n, K=128)
        const int c = t >> 3, r = t & 7, mb = r >> 2, nb = r & 3;
        small_gemmK(Wx + (size_t)c * F_ * HX_ + mb * 64 * HX_, HX_,
                    g_Wihq + (size_t)c * HX_ * H_ + nb * 64, H_,
                    g_WxI + (size_t)c * F_ * H_ + mb * 64 * H_ + nb * 64, H_,
                    64, 64, HX_, nullptr, 0);
    } else if (t < 36) {               // WxO = Wx@Wxo (2m x 2n, K=128)
        const int u = t - 24, c = u >> 2, r = u & 3, mb = r >> 1, nb = r & 1;
        small_gemmK(Wx + (size_t)c * F_ * HX_ + mb * 64 * HX_, HX_,
                    g_Wxo + (size_t)c * HX_ * F_ + nb * 64, F_,
                    g_WxO + (size_t)c * F_ * F_ + mb * 64 * F_ + nb * 64, F_,
                    64, 64, HX_, nullptr, 0);
    } else {                           // bihq2, bo3
        const int c = t - 36;
        small_gemmK(bx + c * HX_, HX_, g_Wihq + (size_t)c * HX_ * H_, H_,
                    g_bihq2 + c * H_, H_, 1, H_, HX_, g_bihq + c * H_, 0);
        small_gemmK(bx + c * HX_, HX_, g_Wxo + (size_t)c * HX_ * F_, F_,
                    g_bo3 + c * F_, F_, 1, F_, HX_, g_bo2 + c * F_, 0);
    }
}

// ===========================================================================
// Parallel GEMM machinery (kernels A and C)
// ===========================================================================
__device__ __forceinline__ void gemm64(const float* __restrict__ As,
                                       const float* __restrict__ Ws,
                                       int k0, float acc[8][8]) {
    const int tc = threadIdx.x & 15;
    const int tr = threadIdx.x >> 4;
    const float* ap = As + tr * 8 * 128 + k0;
    const float* bp = Ws + tc * 8;
#pragma unroll 4
    for (int k = 0; k < 64; ++k) {
        const float4 b0 = *reinterpret_cast<const float4*>(bp + k * 128);
        const float4 b1 = *reinterpret_cast<const float4*>(bp + k * 128 + 4);
        float a[8];
#pragma unroll
        for (int i = 0; i < 8; ++i) a[i] = ap[i * 128 + k];
        const float bv[8] = {b0.x, b0.y, b0.z, b0.w, b1.x, b1.y, b1.z, b1.w};
#pragma unroll
        for (int i = 0; i < 8; ++i)
#pragma unroll
            for (int j = 0; j < 8; ++j)
                acc[i][j] = fmaf(a[i], bv[j], acc[i][j]);
    }
}

// Load a 128x128 fp32 tile (row stride ld) into smem
__device__ __forceinline__ void load_tile(float* dst, const float* __restrict__ src,
                                          int ld) {
    for (int idx = threadIdx.x; idx < 128 * 32; idx += 256) {
        const int r = idx >> 5;
        const int c4 = idx & 31;
        reinterpret_cast<float4*>(dst)[(r << 5) + c4] =
            *reinterpret_cast<const float4*>(src + (size_t)r * ld + (c4 << 2));
    }
}

// Load a 64x128 fp32 slab (row stride ld) into smem
__device__ __forceinline__ void load_half(float* dst, const float* __restrict__ src,
                                          int ld) {
    for (int idx = threadIdx.x; idx < 64 * 32; idx += 256) {
        const int r = idx >> 5;
        const int c4 = idx & 31;
        reinterpret_cast<float4*>(dst)[(r << 5) + c4] =
            *reinterpret_cast<const float4*>(src + (size_t)r * ld + (c4 << 2));
    }
}

__device__ __forceinline__ void zero_acc(float acc[8][8]) {
#pragma unroll
    for (int i = 0; i < 8; ++i)
#pragma unroll
        for (int j = 0; j < 8; ++j) acc[i][j] = 0.f;
}

// full 128-deep GEMM as two 64-row slabs streamed through Ws
__device__ __forceinline__ void gemm128_slabs(const float* As, float* Ws,
                                              const float* __restrict__ W,
                                              int ldw, float acc[8][8]) {
#pragma unroll
    for (int h = 0; h < 2; ++h) {
        load_half(Ws, W + (size_t)(h * 64) * ldw, ldw);
        __syncthreads();
        gemm64(As, Ws, h * 64, acc);
        __syncthreads();
    }
}

// ---------------------------------------------------------------------------
// Kernel A: PO = x@WxO + bo3; PI = x@WxI + bihq2   (3 gemm units per tile)
// grid (4 btiles, T, C), 256 threads, 96KB dynamic smem
// ---------------------------------------------------------------------------
__global__ void __launch_bounds__(256, 2) kernelA(const float* __restrict__ x) {
    extern __shared__ float sm[];
    float* As = sm;                // 128x128
    float* Ws = sm + 128 * 128;    // 8192-float slab
    const int bt = blockIdx.x, t = blockIdx.y, c = blockIdx.z;
    const long rg0 = ((long)(c * T_ + t) * B_ + bt * 128);
    const int tc = threadIdx.x & 15, tr = threadIdx.x >> 4;

    load_tile(As, x + rg0 * F_, F_);   // ordered by sync inside gemm128_slabs

    float acc[8][8];

    // PO = x @ WxO + bo3
    zero_acc(acc);
    gemm128_slabs(As, Ws, g_WxO + (size_t)c * F_ * F_, F_, acc);
#pragma unroll
    for (int i = 0; i < 8; ++i)
#pragma unroll
        for (int j = 0; j < 8; ++j)
            g_PO[(rg0 + tr * 8 + i) * F_ + tc * 8 + j] =
                acc[i][j] + g_bo3[c * F_ + tc * 8 + j];

    // PI = x @ WxI + bihq2 (two 128-col halves)
#pragma unroll
    for (int half = 0; half < 2; ++half) {
        zero_acc(acc);
        gemm128_slabs(As, Ws, g_WxI + (size_t)c * F_ * H_ + half * 128, H_, acc);
#pragma unroll
        for (int i = 0; i < 8; ++i)
#pragma unroll
            for (int j = 0; j < 8; ++j) {
                const int n = half * 128 + tc * 8 + j;
                g_PI[(rg0 + tr * 8 + i) * H_ + n] =
                    acc[i][j] + g_bihq2[c * H_ + n];
            }
    }
}

// ===========================================================================
// Kernel B: pure recurrence with packed fp32x2 math.
// Thread owns ONE output column n; acc lanes = (even-k, odd-k) partial sums.
// Weights read k-contiguously from Whh2T (rows 0..127 staged in smem,
// padded stride 260 to break the 32-way bank conflict).
// hs is ping-pong double-buffered -> ONE barrier per step.
// ===========================================================================
__device__ __forceinline__ float fast_tanh(float x) {
    // tanh(x) = 1 - 2/(exp(2x)+1); safe at +/-inf, abs err ~1e-7
    const float e = __expf(2.f * x);
    return 1.f - __fdividef(2.f, e + 1.f);
}

#define WSM_LD 260   // padded row stride (floats) for staged W2T rows

__global__ void __launch_bounds__(256, 1) kernelB(const float* __restrict__ h0) {
    // dynamic smem: hsA[2816] | hsB[2816] | wsm[128*260]  -> 152 KB
    extern __shared__ float smb[];
    float* hsA = smb;
    float* hsB = smb + RMAX_ * H_;
    float* wsm = smb + 2 * RMAX_ * H_;

    const int c = blockIdx.y;
    // overlapping coverage: 47 CTAs x 11 rows = 517 >= 512; duplicated rows
    // compute bit-identical values, duplicate global stores are benign.
    const int r0 = (blockIdx.x * (B_ - RMAX_)) / (NB_ - 1);
    const int tid = threadIdx.x;

    const float* W2T = g_Whh2T + (size_t)c * H_ * H_;

    for (int idx = tid; idx < RMAX_ * H_; idx += 256)
        hsA[idx] = h0[(size_t)(c * B_ + r0) * H_ + idx];
    // stage rows 0..127 of W2T (padded stride)
    for (int idx = tid; idx < 128 * 64; idx += 256) {
        const int r = idx >> 6, c4 = idx & 63;
        *reinterpret_cast<float4*>(wsm + r * WSM_LD + c4 * 4) =
            *reinterpret_cast<const float4*>(W2T + (size_t)r * H_ + c4 * 4);
    }
    __syncthreads();

    const float* wrow = (tid < 128) ? wsm + (size_t)tid * WSM_LD
                                    : W2T + (size_t)tid * H_;
    float* cur = hsA;
    float* nxt = hsB;

    long rg0 = (long)c * T_ * B_ + r0;
    for (int t = 0; t < T_; ++t, rg0 += B_) {
        // prefetch this step's PI column (coalesced; overlaps with FMAs)
        float pip[RMAX_];
#pragma unroll
        for (int r = 0; r < RMAX_; ++r)
            pip[r] = g_PI[(rg0 + r) * H_ + tid];

        unsigned long long acc2[RMAX_];
#pragma unroll
        for (int r = 0; r < RMAX_; ++r) acc2[r] = 0ull;

        // k-loop: per 4-k batch: 1 w-load (2 x f32x2) + RMAX_ a-loads + 2*RMAX_ FMA2
        ulonglong2 w = *reinterpret_cast<const ulonglong2*>(wrow);
#pragma unroll 2
        for (int k = 0; k < H_; k += 4) {
            ulonglong2 wn;
            if (k + 4 < H_)
                wn = *reinterpret_cast<const ulonglong2*>(wrow + k + 4);
#pragma unroll
            for (int r = 0; r < RMAX_; ++r) {
                const ulonglong2 a =
                    *reinterpret_cast<const ulonglong2*>(cur + r * H_ + k);
                FMA2(acc2[r], a.x, w.x, acc2[r]);
                FMA2(acc2[r], a.y, w.y, acc2[r]);
            }
            w = wn;
        }

        // store Hs[t] = h (pre-update) while FMAs drain
        for (int idx = tid; idx < RMAX_ * H_ / 4; idx += 256)
            reinterpret_cast<float4*>(&g_Hs[rg0 * H_])[idx] =
                reinterpret_cast<const float4*>(cur)[idx];

        // horizontal add + PI + tanh -> next h (writes only nxt: no race)
#pragma unroll
        for (int r = 0; r < RMAX_; ++r) {
            const float lo = __uint_as_float((unsigned)acc2[r]);
            const float hi = __uint_as_float((unsigned)(acc2[r] >> 32));
            nxt[r * H_ + tid] = fast_tanh(lo + hi + pip[r]);
        }
        __syncthreads();
        float* tmp = cur; cur = nxt; nxt = tmp;
    }
}

// ---------------------------------------------------------------------------
// Kernel C: out = PO + Hs@Who2
// grid (4 btiles, T, C), 256 threads, 96KB dynamic smem
// ---------------------------------------------------------------------------
__global__ void __launch_bounds__(256, 2) kernelC(float* __restrict__ out) {
    extern __shared__ float sm[];
    float* As = sm;
    float* Ws = sm + 128 * 128;
    const int bt = blockIdx.x, t = blockIdx.y, c = blockIdx.z;
    const long rg0 = ((long)(c * T_ + t) * B_ + bt * 128);
    const int tc = threadIdx.x & 15, tr = threadIdx.x >> 4;

    float acc[8][8];
    zero_acc(acc);

    // h part: two 128-row slices of Who2 (K=256 total)
    load_tile(As, g_Hs + rg0 * H_, H_);
    gemm128_slabs(As, Ws, g_Who2 + (size_t)c * H_ * F_, F_, acc);
    load_tile(As, g_Hs + rg0 * H_ + 128, H_);
    gemm128_slabs(As, Ws, g_Who2 + (size_t)c * H_ * F_ + 128 * F_, F_, acc);

#pragma unroll
    for (int i = 0; i < 8; ++i)
#pragma unroll
        for (int j = 0; j < 8; ++j) {
            const long o = (rg0 + tr * 8 + i) * F_ + tc * 8 + j;
            out[o] = acc[i][j] + g_PO[o];
        }
}

// ---------------------------------------------------------------------------
extern "C" void kernel_launch(void* const* d_in, const int* in_sizes, int n_in,
                              void* d_out, int out_size) {
    (void)in_sizes; (void)n_in; (void)out_size;
    const float* x        = (const float*)d_in[0];
    const float* phi_x_W  = (const float*)d_in[1];
    const float* phi_x_b  = (const float*)d_in[2];
    const float* enc_W    = (const float*)d_in[3];
    const float* enc_b    = (const float*)d_in[4];
    const float* enc_mu_W = (const float*)d_in[5];
    const float* enc_mu_b = (const float*)d_in[6];
    const float* phi_z_W  = (const float*)d_in[7];
    const float* phi_z_b  = (const float*)d_in[8];
    const float* dec_W    = (const float*)d_in[9];
    const float* dec_b    = (const float*)d_in[10];
    const float* dec_mu_W = (const float*)d_in[11];
    const float* dec_mu_b = (const float*)d_in[12];
    const float* rnn_Wih  = (const float*)d_in[13];
    const float* rnn_Whh  = (const float*)d_in[14];
    const float* rnn_bih  = (const float*)d_in[15];
    const float* rnn_bhh  = (const float*)d_in[16];
    const float* h0       = (const float*)d_in[17];
    float* out = (float*)d_out;

    const size_t smemAC = (128 * 128 + 64 * 128) * sizeof(float);  // 96 KB
    const size_t smemB  = (2 * RMAX_ * H_ + 128 * WSM_LD) * sizeof(float); // 152 KB
    cudaFuncSetAttribute(kernelA, cudaFuncAttributeMaxDynamicSharedMemorySize,
                         (int)smemAC);
    cudaFuncSetAttribute(kernelB, cudaFuncAttributeMaxDynamicSharedMemorySize,
                         (int)smemB);
    cudaFuncSetAttribute(kernelC, cudaFuncAttributeMaxDynamicSharedMemorySize,
                         (int)smemAC);

    kernelF1<<<35, 256>>>(enc_W, enc_b, enc_mu_W, enc_mu_b, phi_z_W, phi_z_b,
                          dec_W, dec_b, rnn_Wih);
    kernelF2<<<108, 256>>>(dec_W, dec_mu_W, dec_mu_b, rnn_Whh, rnn_Wih,
                           rnn_bih, rnn_bhh);
    kernelF3<<<51, 256>>>();
    kernelF4<<<39, 256>>>(phi_x_W, phi_x_b);
    kernelA<<<dim3(4, T_, C_), 256, smemAC>>>(x);
    kernelB<<<dim3(NB_, C_), 256, smemB>>>(h0);
    kernelC<<<dim3(4, T_, C_), 256, smemAC>>>(out);
}

// round 14
// speedup vs baseline: 1.3135x; 1.3135x over previous
#include <cuda_runtime.h>
#include <math.h>

// Problem dims
#define C_   3
#define T_   100
#define B_   512
#define F_   128
#define HX_  128
#define HZ_  128
#define H_   256
#define EH_  128
#define L_   64

#define NB_   86   // CTAs per channel (86*6=516 >= 512; 258 CTAs, 2/SM)
#define RMAX_ 6    // rows per CTA

// packed fp32x2 FMA (sm_100+): d = a*b + c on two fp32 lanes
#define FMA2(d, a, b, c) \
    asm("fma.rn.f32x2 %0, %1, %2, %3;" : "=l"(d) : "l"(a), "l"(b), "l"(c))

__device__ __forceinline__ unsigned long long dup2(float v) {
    unsigned long long d;
    const unsigned u = __float_as_uint(v);
    asm("mov.b64 %0, {%1, %1};" : "=l"(d) : "r"(u));
    return d;
}
__device__ __forceinline__ float2 unpack2(unsigned long long v) {
    return make_float2(__uint_as_float((unsigned)v),
                       __uint_as_float((unsigned)(v >> 32)));
}

// ---- big activations scratch ----
__device__ float g_PI[(size_t)C_ * T_ * B_ * H_];   // x@WxI + bihq2
__device__ float g_PO[(size_t)C_ * T_ * B_ * F_];   // x@WxO + bo3
__device__ float g_Hs[(size_t)C_ * T_ * B_ * H_];   // h at step input

// ---- folded weights (computed on-device each run; tiny) ----
__device__ float g_Weq[C_ * HX_ * L_];
__device__ float g_beq[C_ * L_];
__device__ float g_Wcomb[C_ * H_ * L_];
__device__ float g_Wihz[L_ * H_];
__device__ float g_bihz[H_];
__device__ float g_Wdz[C_ * L_ * EH_];
__device__ float g_bdz[C_ * EH_];
__device__ float g_Wzo[C_ * L_ * F_];
__device__ float g_Who[C_ * H_ * F_];
__device__ float g_bo[C_ * F_];
__device__ float g_Whh2[C_ * H_ * H_];
__device__ float g_Wihq[C_ * HX_ * H_];
__device__ float g_bihq[C_ * H_];
__device__ float g_Who2[C_ * H_ * F_];
__device__ float g_Wxo[C_ * HX_ * F_];
__device__ float g_bo2[C_ * F_];
__device__ float g_WxI[C_ * F_ * H_];
__device__ float g_bihq2[C_ * H_];
__device__ float g_WxO[C_ * F_ * F_];
__device__ float g_bo3[C_ * F_];

// ===========================================================================
// small GEMM block for weight folding (unchanged from R11/R12)
// ===========================================================================
__device__ __forceinline__ void small_gemmK(const float* __restrict__ A, int lda,
                                            const float* __restrict__ Bm, int ldb,
                                            float* __restrict__ out, int ldo,
                                            int M, int N, int K,
                                            const float* __restrict__ addm,
                                            int ldam) {
    const int M4 = M >> 2;
    const int Nq = N >> 2;
    for (int idx = threadIdx.x; idx < M4 * Nq; idx += 256) {
        const int mg = idx / Nq, ng = idx % Nq;
        const int m = mg * 4, n = ng * 4;
        float4 s0, s1, s2, s3;
        if (addm) {
            s0 = *reinterpret_cast<const float4*>(addm + (size_t)(m + 0) * ldam + n);
            s1 = *reinterpret_cast<const float4*>(addm + (size_t)(m + 1) * ldam + n);
            s2 = *reinterpret_cast<const float4*>(addm + (size_t)(m + 2) * ldam + n);
            s3 = *reinterpret_cast<const float4*>(addm + (size_t)(m + 3) * ldam + n);
        } else {
            s0 = s1 = s2 = s3 = make_float4(0.f, 0.f, 0.f, 0.f);
        }
        const float* a0 = A + (size_t)(m + 0) * lda;
        const float* a1 = A + (size_t)(m + 1) * lda;
        const float* a2 = A + (size_t)(m + 2) * lda;
        const float* a3 = A + (size_t)(m + 3) * lda;
        const float* b = Bm + n;
#pragma unroll 4
        for (int k = 0; k < K; ++k) {
            const float4 bv = *reinterpret_cast<const float4*>(b + (size_t)k * ldb);
            const float v0 = a0[k], v1 = a1[k], v2 = a2[k], v3 = a3[k];
            s0.x = fmaf(v0, bv.x, s0.x); s0.y = fmaf(v0, bv.y, s0.y);
            s0.z = fmaf(v0, bv.z, s0.z); s0.w = fmaf(v0, bv.w, s0.w);
            s1.x = fmaf(v1, bv.x, s1.x); s1.y = fmaf(v1, bv.y, s1.y);
            s1.z = fmaf(v1, bv.z, s1.z); s1.w = fmaf(v1, bv.w, s1.w);
            s2.x = fmaf(v2, bv.x, s2.x); s2.y = fmaf(v2, bv.y, s2.y);
            s2.z = fmaf(v2, bv.z, s2.z); s2.w = fmaf(v2, bv.w, s2.w);
            s3.x = fmaf(v3, bv.x, s3.x); s3.y = fmaf(v3, bv.y, s3.y);
            s3.z = fmaf(v3, bv.z, s3.z); s3.w = fmaf(v3, bv.w, s3.w);
        }
        *reinterpret_cast<float4*>(out + (size_t)(m + 0) * ldo + n) = s0;
        *reinterpret_cast<float4*>(out + (size_t)(m + 1) * ldo + n) = s1;
        *reinterpret_cast<float4*>(out + (size_t)(m + 2) * ldo + n) = s2;
        *reinterpret_cast<float4*>(out + (size_t)(m + 3) * ldo + n) = s3;
    }
    const int mrem0 = M4 * 4;
    for (int idx = threadIdx.x; idx < (M - mrem0) * N; idx += 256) {
        const int m = mrem0 + idx / N, n = idx % N;
        float s = addm ? addm[(size_t)m * ldam + n] : 0.f;
        const float* a = A + (size_t)m * lda;
        const float* b = Bm + n;
#pragma unroll 4
        for (int k = 0; k < K; ++k) s = fmaf(a[k], b[(size_t)k * ldb], s);
        out[(size_t)m * ldo + n] = s;
    }
}

// fold stage 1 (35 CTAs)
__global__ void __launch_bounds__(256) kernelF1(
    const float* __restrict__ We, const float* __restrict__ be,
    const float* __restrict__ Wqm, const float* __restrict__ bqm,
    const float* __restrict__ Wzp, const float* __restrict__ bzp,
    const float* __restrict__ Wd, const float* __restrict__ bd,
    const float* __restrict__ Wih) {
    const int t = blockIdx.x;
    if (t < 6) {
        const int c = t >> 1, mb = t & 1;
        small_gemmK(We + (size_t)c * 384 * EH_ + mb * 64 * EH_, EH_,
                    Wqm + (size_t)c * EH_ * L_, L_,
                    g_Weq + c * HX_ * L_ + mb * 64 * L_, L_, 64, L_, EH_,
                    nullptr, 0);
    } else if (t < 18) {
        const int u = t - 6, c = u >> 2, mb = u & 3;
        small_gemmK(We + (size_t)c * 384 * EH_ + (128 + mb * 64) * EH_, EH_,
                    Wqm + (size_t)c * EH_ * L_, L_,
                    g_Wcomb + c * H_ * L_ + mb * 64 * L_, L_, 64, L_, EH_,
                    nullptr, 0);
    } else if (t < 24) {
        const int u = t - 18, c = u >> 1, nb = u & 1;
        small_gemmK(Wzp, HZ_, Wd + (size_t)c * 384 * EH_ + nb * 64, EH_,
                    g_Wdz + c * L_ * EH_ + nb * 64, EH_, L_, 64, HZ_,
                    nullptr, 0);
    } else if (t < 28) {
        const int nb = t - 24;
        small_gemmK(Wzp, HZ_, Wih + 128 * H_ + nb * 64, H_,
                    g_Wihz + nb * 64, H_, L_, 64, HZ_, nullptr, 0);
    } else if (t < 31) {
        const int c = t - 28;
        small_gemmK(be + c * EH_, EH_, Wqm + (size_t)c * EH_ * L_, L_,
                    g_beq + c * L_, L_, 1, L_, EH_, bqm + c * L_, 0);
    } else if (t < 34) {
        const int c = t - 31;
        small_gemmK(bzp, HZ_, Wd + (size_t)c * 384 * EH_, EH_,
                    g_bdz + c * EH_, EH_, 1, EH_, HZ_, bd + c * EH_, 0);
    } else {
        small_gemmK(bzp, HZ_, Wih + 128 * H_, H_, g_bihz, H_, 1, H_, HZ_,
                    nullptr, 0);
    }
}

// fold stage 2 (108 CTAs)
__global__ void __launch_bounds__(256) kernelF2(
    const float* __restrict__ Wd, const float* __restrict__ Wpm,
    const float* __restrict__ bpm, const float* __restrict__ Whh,
    const float* __restrict__ Wih, const float* __restrict__ bih,
    const float* __restrict__ bhh) {
    const int t = blockIdx.x;
    if (t < 6) {
        const int c = t >> 1, nb = t & 1;
        small_gemmK(g_Wdz + c * L_ * EH_, EH_,
                    Wpm + (size_t)c * EH_ * F_ + nb * 64, F_,
                    g_Wzo + c * L_ * F_ + nb * 64, F_, L_, 64, EH_, nullptr, 0);
    } else if (t < 30) {
        const int u = t - 6, c = u >> 3, r = u & 7, mb = r >> 1, nb = r & 1;
        small_gemmK(Wd + (size_t)c * 384 * EH_ + (128 + mb * 64) * EH_, EH_,
                    Wpm + (size_t)c * EH_ * F_ + nb * 64, F_,
                    g_Who + c * H_ * F_ + mb * 64 * F_ + nb * 64, F_,
                    64, 64, EH_, nullptr, 0);
    } else if (t < 33) {
        const int c = t - 30;
        small_gemmK(g_bdz + c * EH_, EH_, Wpm + (size_t)c * EH_ * F_, F_,
                    g_bo + c * F_, F_, 1, F_, EH_, bpm + c * F_, 0);
    } else if (t < 81) {
        const int u = t - 33, c = u >> 4, r = u & 15, mb = r >> 2, nb = r & 3;
        small_gemmK(g_Wcomb + c * H_ * L_ + mb * 64 * L_, L_,
                    g_Wihz + nb * 64, H_,
                    g_Whh2 + (size_t)c * H_ * H_ + mb * 64 * H_ + nb * 64, H_,
                    64, 64, L_, Whh + (size_t)mb * 64 * H_ + nb * 64, H_);
    } else if (t < 105) {
        const int u = t - 81, c = u >> 3, r = u & 7, mb = r >> 2, nb = r & 3;
        small_gemmK(g_Weq + c * HX_ * L_ + mb * 64 * L_, L_,
                    g_Wihz + nb * 64, H_,
                    g_Wihq + (size_t)c * HX_ * H_ + mb * 64 * H_ + nb * 64, H_,
                    64, 64, L_, Wih + (size_t)mb * 64 * H_ + nb * 64, H_);
    } else {
        const int c = t - 105;
        for (int n = threadIdx.x; n < H_; n += 256) {
            float s = bih[n] + bhh[n] + g_bihz[n];
            for (int l = 0; l < L_; ++l)
                s = fmaf(g_beq[c * L_ + l], g_Wihz[l * H_ + n], s);
            g_bihq[c * H_ + n] = s;
        }
    }
}

// fold stage 3 (39 CTAs)
__global__ void __launch_bounds__(256) kernelF3() {
    const int t = blockIdx.x;
    if (t < 24) {
        const int c = t >> 3, r = t & 7, mb = r >> 1, nb = r & 1;
        small_gemmK(g_Wcomb + c * H_ * L_ + mb * 64 * L_, L_,
                    g_Wzo + c * L_ * F_ + nb * 64, F_,
                    g_Who2 + c * H_ * F_ + mb * 64 * F_ + nb * 64, F_,
                    64, 64, L_,
                    g_Who + c * H_ * F_ + mb * 64 * F_ + nb * 64, F_);
    } else if (t < 36) {
        const int u = t - 24, c = u >> 2, r = u & 3, mb = r >> 1, nb = r & 1;
        small_gemmK(g_Weq + c * HX_ * L_ + mb * 64 * L_, L_,
                    g_Wzo + c * L_ * F_ + nb * 64, F_,
                    g_Wxo + c * HX_ * F_ + mb * 64 * F_ + nb * 64, F_,
                    64, 64, L_, nullptr, 0);
    } else {
        const int c = t - 36;
        small_gemmK(g_beq + c * L_, L_, g_Wzo + c * L_ * F_, F_,
                    g_bo2 + c * F_, F_, 1, F_, L_, g_bo + c * F_, 0);
    }
}

// fold stage 4 (39 CTAs)
__global__ void __launch_bounds__(256) kernelF4(
    const float* __restrict__ Wx, const float* __restrict__ bx) {
    const int t = blockIdx.x;
    if (t < 24) {
        const int c = t >> 3, r = t & 7, mb = r >> 2, nb = r & 3;
        small_gemmK(Wx + (size_t)c * F_ * HX_ + mb * 64 * HX_, HX_,
                    g_Wihq + (size_t)c * HX_ * H_ + nb * 64, H_,
                    g_WxI + (size_t)c * F_ * H_ + mb * 64 * H_ + nb * 64, H_,
                    64, 64, HX_, nullptr, 0);
    } else if (t < 36) {
        const int u = t - 24, c = u >> 2, r = u & 3, mb = r >> 1, nb = r & 1;
        small_gemmK(Wx + (size_t)c * F_ * HX_ + mb * 64 * HX_, HX_,
                    g_Wxo + (size_t)c * HX_ * F_ + nb * 64, F_,
                    g_WxO + (size_t)c * F_ * F_ + mb * 64 * F_ + nb * 64, F_,
                    64, 64, HX_, nullptr, 0);
    } else {
        const int c = t - 36;
        small_gemmK(bx + c * HX_, HX_, g_Wihq + (size_t)c * HX_ * H_, H_,
                    g_bihq2 + c * H_, H_, 1, H_, HX_, g_bihq + c * H_, 0);
        small_gemmK(bx + c * HX_, HX_, g_Wxo + (size_t)c * HX_ * F_, F_,
                    g_bo3 + c * F_, F_, 1, F_, HX_, g_bo2 + c * F_, 0);
    }
}

// ===========================================================================
// Parallel GEMM machinery (kernels A and C) — packed f32x2 math.
// acc2[i][p]: p-th pair of output columns for row i (lanes = cols 2p, 2p+1).
// Same loads and accumulation order as the FFMA version -> identical results.
// ===========================================================================
__device__ __forceinline__ void gemm64(const float* __restrict__ As,
                                       const float* __restrict__ Ws,
                                       int k0, unsigned long long acc2[8][4]) {
    const int tc = threadIdx.x & 15;
    const int tr = threadIdx.x >> 4;
    const float* ap = As + tr * 8 * 128 + k0;
    const float* bp = Ws + tc * 8;
#pragma unroll 4
    for (int k = 0; k < 64; ++k) {
        const ulonglong2 b01 = *reinterpret_cast<const ulonglong2*>(bp + k * 128);
        const ulonglong2 b23 = *reinterpret_cast<const ulonglong2*>(bp + k * 128 + 4);
#pragma unroll
        for (int i = 0; i < 8; ++i) {
            const unsigned long long ai = dup2(ap[i * 128 + k]);
            FMA2(acc2[i][0], ai, b01.x, acc2[i][0]);
            FMA2(acc2[i][1], ai, b01.y, acc2[i][1]);
            FMA2(acc2[i][2], ai, b23.x, acc2[i][2]);
            FMA2(acc2[i][3], ai, b23.y, acc2[i][3]);
        }
    }
}

// Load a 128x128 fp32 tile (row stride ld) into smem
__device__ __forceinline__ void load_tile(float* dst, const float* __restrict__ src,
                                          int ld) {
    for (int idx = threadIdx.x; idx < 128 * 32; idx += 256) {
        const int r = idx >> 5;
        const int c4 = idx & 31;
        reinterpret_cast<float4*>(dst)[(r << 5) + c4] =
            *reinterpret_cast<const float4*>(src + (size_t)r * ld + (c4 << 2));
    }
}

// Load a 64x128 fp32 slab (row stride ld) into smem
__device__ __forceinline__ void load_half(float* dst, const float* __restrict__ src,
                                          int ld) {
    for (int idx = threadIdx.x; idx < 64 * 32; idx += 256) {
        const int r = idx >> 5;
        const int c4 = idx & 31;
        reinterpret_cast<float4*>(dst)[(r << 5) + c4] =
            *reinterpret_cast<const float4*>(src + (size_t)r * ld + (c4 << 2));
    }
}

__device__ __forceinline__ void zero_acc2(unsigned long long acc2[8][4]) {
#pragma unroll
    for (int i = 0; i < 8; ++i)
#pragma unroll
        for (int p = 0; p < 4; ++p) acc2[i][p] = 0ull;
}

// full 128-deep GEMM as two 64-row slabs streamed through Ws
__device__ __forceinline__ void gemm128_slabs(const float* As, float* Ws,
                                              const float* __restrict__ W,
                                              int ldw,
                                              unsigned long long acc2[8][4]) {
#pragma unroll
    for (int h = 0; h < 2; ++h) {
        load_half(Ws, W + (size_t)(h * 64) * ldw, ldw);
        __syncthreads();
        gemm64(As, Ws, h * 64, acc2);
        __syncthreads();
    }
}

// ---------------------------------------------------------------------------
// Kernel A: PO = x@WxO + bo3; PI = x@WxI + bihq2
// ---------------------------------------------------------------------------
__global__ void __launch_bounds__(256, 2) kernelA(const float* __restrict__ x) {
    extern __shared__ float sm[];
    float* As = sm;
    float* Ws = sm + 128 * 128;
    const int bt = blockIdx.x, t = blockIdx.y, c = blockIdx.z;
    const long rg0 = ((long)(c * T_ + t) * B_ + bt * 128);
    const int tc = threadIdx.x & 15, tr = threadIdx.x >> 4;

    load_tile(As, x + rg0 * F_, F_);

    unsigned long long acc2[8][4];

    // PO = x @ WxO + bo3
    zero_acc2(acc2);
    gemm128_slabs(As, Ws, g_WxO + (size_t)c * F_ * F_, F_, acc2);
#pragma unroll
    for (int i = 0; i < 8; ++i)
#pragma unroll
        for (int p = 0; p < 4; ++p) {
            const float2 f = unpack2(acc2[i][p]);
            const int n = tc * 8 + 2 * p;
            g_PO[(rg0 + tr * 8 + i) * F_ + n]     = f.x + g_bo3[c * F_ + n];
            g_PO[(rg0 + tr * 8 + i) * F_ + n + 1] = f.y + g_bo3[c * F_ + n + 1];
        }

    // PI = x @ WxI + bihq2 (two 128-col halves)
#pragma unroll
    for (int half = 0; half < 2; ++half) {
        zero_acc2(acc2);
        gemm128_slabs(As, Ws, g_WxI + (size_t)c * F_ * H_ + half * 128, H_, acc2);
#pragma unroll
        for (int i = 0; i < 8; ++i)
#pragma unroll
            for (int p = 0; p < 4; ++p) {
                const float2 f = unpack2(acc2[i][p]);
                const int n = half * 128 + tc * 8 + 2 * p;
                g_PI[(rg0 + tr * 8 + i) * H_ + n] =
                    f.x + g_bihq2[c * H_ + n];
                g_PI[(rg0 + tr * 8 + i) * H_ + n + 1] =
                    f.y + g_bihq2[c * H_ + n + 1];
            }
    }
}

// ===========================================================================
// Kernel B: R11 structure (mm4s, p0 partition in smem, scr reduce),
// arithmetic swapped to packed f32x2. Identical loads & accumulation order.
// ===========================================================================
__device__ __forceinline__ float fast_tanh(float x) {
    const float e = __expf(2.f * x);
    return 1.f - __fdividef(2.f, e + 1.f);
}

// K=256, N=256 (G=64, P=4, Ks=64); p==0 reads weights from smem copy.
// acc01[r]/acc23[r] = packed pairs of this thread's 4 output columns.
__device__ __forceinline__ void mm4s(const float* __restrict__ Wg,
                                     const float* __restrict__ Wsm,
                                     const float* __restrict__ a_s,
                                     unsigned long long acc01[RMAX_],
                                     unsigned long long acc23[RMAX_]) {
    constexpr int G = 64;   // N/4
    constexpr int Ks = 64;  // K/P
    const int g = threadIdx.x % G;
    const int p = threadIdx.x / G;
    const ulonglong2* wp = (p == 0)
        ? reinterpret_cast<const ulonglong2*>(Wsm) + g
        : reinterpret_cast<const ulonglong2*>(Wg) + (size_t)(p * Ks) * G + g;
    const float* ap = a_s + p * Ks;

    ulonglong2 w0 = wp[0 * G], w1 = wp[1 * G], w2 = wp[2 * G], w3 = wp[3 * G];
#pragma unroll 1
    for (int k = 0; k < Ks; k += 4) {
        ulonglong2 n0, n1, n2, n3;
        if (k + 4 < Ks) {
            n0 = wp[(k + 4) * G];
            n1 = wp[(k + 5) * G];
            n2 = wp[(k + 6) * G];
            n3 = wp[(k + 7) * G];
        }
#pragma unroll
        for (int r = 0; r < RMAX_; ++r) {
            const float4 a = *reinterpret_cast<const float4*>(ap + r * 256 + k);
            const unsigned long long ax = dup2(a.x);
            const unsigned long long ay = dup2(a.y);
            const unsigned long long az = dup2(a.z);
            const unsigned long long aw = dup2(a.w);
            FMA2(acc01[r], ax, w0.x, acc01[r]);
            FMA2(acc23[r], ax, w0.y, acc23[r]);
            FMA2(acc01[r], ay, w1.x, acc01[r]);
            FMA2(acc23[r], ay, w1.y, acc23[r]);
            FMA2(acc01[r], az, w2.x, acc01[r]);
            FMA2(acc23[r], az, w2.y, acc23[r]);
            FMA2(acc01[r], aw, w3.x, acc01[r]);
            FMA2(acc23[r], aw, w3.y, acc23[r]);
        }
        w0 = n0; w1 = n1; w2 = n2; w3 = n3;
    }
}

__global__ void __launch_bounds__(256, 2) kernelB(const float* __restrict__ h0) {
    // dynamic smem: hs[1536] | scr2[6144] | wsm[16384]  -> 94 KB
    extern __shared__ float smb[];
    float* hs   = smb;
    float* scr2 = smb + RMAX_ * H_;
    float* wsm  = scr2 + 4 * RMAX_ * 256;

    const int c = blockIdx.y;
    const int r0 = (blockIdx.x * (B_ - RMAX_)) / (NB_ - 1);
    const int tid = threadIdx.x;

    const float* Whh2 = g_Whh2 + (size_t)c * H_ * H_;

    for (int idx = tid; idx < RMAX_ * H_; idx += 256)
        hs[idx] = h0[(size_t)(c * B_ + r0) * H_ + idx];
    // stage rows 0..63 of Whh2 (the p=0 k-partition) into smem
    for (int idx = tid; idx < 64 * 256 / 4; idx += 256)
        reinterpret_cast<float4*>(wsm)[idx] =
            reinterpret_cast<const float4*>(Whh2)[idx];
    __syncthreads();

    unsigned long long acc01[RMAX_], acc23[RMAX_];
    const int g = tid % 64, p = tid / 64;

    long rg0 = (long)c * T_ * B_ + r0;
    for (int t = 0; t < T_; ++t, rg0 += B_) {
        // prefetch this step's PI into registers (overlaps with FMAs below)
        float pip[RMAX_];
#pragma unroll
        for (int j = 0; j < RMAX_; ++j)
            pip[j] = g_PI[rg0 * H_ + j * 256 + tid];

#pragma unroll
        for (int r = 0; r < RMAX_; ++r) { acc01[r] = 0ull; acc23[r] = 0ull; }
        mm4s(Whh2, wsm, hs, acc01, acc23);
        // store partials (same bytes as the float4 stores of R11)
#pragma unroll
        for (int r = 0; r < RMAX_; ++r) {
            ulonglong2 v; v.x = acc01[r]; v.y = acc23[r];
            *reinterpret_cast<ulonglong2*>(
                scr2 + (size_t)(p * RMAX_ + r) * 256 + 4 * g) = v;
        }
        // store Hs[t] = h (pre-update) while partials land
        for (int idx = tid; idx < RMAX_ * H_ / 4; idx += 256)
            reinterpret_cast<float4*>(&g_Hs[rg0 * H_])[idx] =
                reinterpret_cast<const float4*>(hs)[idx];
        __syncthreads();

        // reduce 4 partials + PI -> tanh -> hs (1536 outputs)
#pragma unroll
        for (int j = 0; j < RMAX_; ++j) {
            const int idx = j * 256 + tid;
            const int r = idx >> 8;
            const int n = idx & 255;
            float s = pip[j];
#pragma unroll
            for (int q = 0; q < 4; ++q)
                s += scr2[(size_t)(q * RMAX_ + r) * 256 + n];
            hs[idx] = fast_tanh(s);
        }
        __syncthreads();
    }
}

// ---------------------------------------------------------------------------
// Kernel C: out = PO + Hs@Who2
// ---------------------------------------------------------------------------
__global__ void __launch_bounds__(256, 2) kernelC(float* __restrict__ out) {
    extern __shared__ float sm[];
    float* As = sm;
    float* Ws = sm + 128 * 128;
    const int bt = blockIdx.x, t = blockIdx.y, c = blockIdx.z;
    const long rg0 = ((long)(c * T_ + t) * B_ + bt * 128);
    const int tc = threadIdx.x & 15, tr = threadIdx.x >> 4;

    unsigned long long acc2[8][4];
    zero_acc2(acc2);

    // h part: two 128-row slices of Who2 (K=256 total)
    load_tile(As, g_Hs + rg0 * H_, H_);
    gemm128_slabs(As, Ws, g_Who2 + (size_t)c * H_ * F_, F_, acc2);
    load_tile(As, g_Hs + rg0 * H_ + 128, H_);
    gemm128_slabs(As, Ws, g_Who2 + (size_t)c * H_ * F_ + 128 * F_, F_, acc2);

#pragma unroll
    for (int i = 0; i < 8; ++i)
#pragma unroll
        for (int p = 0; p < 4; ++p) {
            const float2 f = unpack2(acc2[i][p]);
            const long o = (rg0 + tr * 8 + i) * F_ + tc * 8 + 2 * p;
            out[o]     = f.x + g_PO[o];
            out[o + 1] = f.y + g_PO[o + 1];
        }
}

// ---------------------------------------------------------------------------
extern "C" void kernel_launch(void* const* d_in, const int* in_sizes, int n_in,
                              void* d_out, int out_size) {
    (void)in_sizes; (void)n_in; (void)out_size;
    const float* x        = (const float*)d_in[0];
    const float* phi_x_W  = (const float*)d_in[1];
    const float* phi_x_b  = (const float*)d_in[2];
    const float* enc_W    = (const float*)d_in[3];
    const float* enc_b    = (const float*)d_in[4];
    const float* enc_mu_W = (const float*)d_in[5];
    const float* enc_mu_b = (const float*)d_in[6];
    const float* phi_z_W  = (const float*)d_in[7];
    const float* phi_z_b  = (const float*)d_in[8];
    const float* dec_W    = (const float*)d_in[9];
    const float* dec_b    = (const float*)d_in[10];
    const float* dec_mu_W = (const float*)d_in[11];
    const float* dec_mu_b = (const float*)d_in[12];
    const float* rnn_Wih  = (const float*)d_in[13];
    const float* rnn_Whh  = (const float*)d_in[14];
    const float* rnn_bih  = (const float*)d_in[15];
    const float* rnn_bhh  = (const float*)d_in[16];
    const float* h0       = (const float*)d_in[17];
    float* out = (float*)d_out;

    const size_t smemAC = (128 * 128 + 64 * 128) * sizeof(float);  // 96 KB
    const size_t smemB  = (RMAX_ * H_ + 4 * RMAX_ * 256 + 64 * 256)
                          * sizeof(float);                          // 94 KB
    cudaFuncSetAttribute(kernelA, cudaFuncAttributeMaxDynamicSharedMemorySize,
                         (int)smemAC);
    cudaFuncSetAttribute(kernelB, cudaFuncAttributeMaxDynamicSharedMemorySize,
                         (int)smemB);
    cudaFuncSetAttribute(kernelC, cudaFuncAttributeMaxDynamicSharedMemorySize,
                         (int)smemAC);

    kernelF1<<<35, 256>>>(enc_W, enc_b, enc_mu_W, enc_mu_b, phi_z_W, phi_z_b,
                          dec_W, dec_b, rnn_Wih);
    kernelF2<<<108, 256>>>(dec_W, dec_mu_W, dec_mu_b, rnn_Whh, rnn_Wih,
                           rnn_bih, rnn_bhh);
    kernelF3<<<39, 256>>>();
    kernelF4<<<39, 256>>>(phi_x_W, phi_x_b);
    kernelA<<<dim3(4, T_, C_), 256, smemAC>>>(x);
    kernelB<<<dim3(NB_, C_), 256, smemB>>>(h0);
    kernelC<<<dim3(4, T_, C_), 256, smemAC>>>(out);
}

// round 15
// speedup vs baseline: 1.3190x; 1.0042x over previous
#include <cuda_runtime.h>
#include <math.h>

// Problem dims
#define C_   3
#define T_   100
#define B_   512
#define F_   128
#define HX_  128
#define HZ_  128
#define H_   256
#define EH_  128
#define L_   64

#define NB_   86   // CTAs per channel (86*6=516 >= 512; 258 CTAs, 2/SM)
#define RMAX_ 6    // rows per CTA

// packed fp32x2 FMA (sm_100+): d = a*b + c on two fp32 lanes
#define FMA2(d, a, b, c) \
    asm("fma.rn.f32x2 %0, %1, %2, %3;" : "=l"(d) : "l"(a), "l"(b), "l"(c))

__device__ __forceinline__ unsigned long long dup2(float v) {
    unsigned long long d;
    const unsigned u = __float_as_uint(v);
    asm("mov.b64 %0, {%1, %1};" : "=l"(d) : "r"(u));
    return d;
}
__device__ __forceinline__ float2 unpack2(unsigned long long v) {
    return make_float2(__uint_as_float((unsigned)v),
                       __uint_as_float((unsigned)(v >> 32)));
}

// ---- big activations scratch ----
__device__ float g_PI[(size_t)C_ * T_ * B_ * H_];   // x@WxI + bihq2
__device__ float g_PO[(size_t)C_ * T_ * B_ * F_];   // x@WxO + bo3
__device__ float g_Hs[(size_t)C_ * T_ * B_ * H_];   // h at step input

// ---- folded weights (computed on-device each run; tiny) ----
__device__ float g_Weq[C_ * HX_ * L_];
__device__ float g_beq[C_ * L_];
__device__ float g_Wcomb[C_ * H_ * L_];
__device__ float g_Wihz[L_ * H_];
__device__ float g_bihz[H_];
__device__ float g_Wdz[C_ * L_ * EH_];
__device__ float g_bdz[C_ * EH_];
__device__ float g_Wzo[C_ * L_ * F_];
__device__ float g_Who[C_ * H_ * F_];
__device__ float g_bo[C_ * F_];
__device__ float g_Whh2[C_ * H_ * H_];
__device__ float g_Wihq[C_ * HX_ * H_];
__device__ float g_bihq[C_ * H_];
__device__ float g_Who2[C_ * H_ * F_];
__device__ float g_Wxo[C_ * HX_ * F_];
__device__ float g_bo2[C_ * F_];
__device__ float g_WxI[C_ * F_ * H_];
__device__ float g_bihq2[C_ * H_];
__device__ float g_WxO[C_ * F_ * F_];
__device__ float g_bo3[C_ * F_];

// ===========================================================================
// small GEMM block for weight folding (unchanged from R11/R12)
// ===========================================================================
__device__ __forceinline__ void small_gemmK(const float* __restrict__ A, int lda,
                                            const float* __restrict__ Bm, int ldb,
                                            float* __restrict__ out, int ldo,
                                            int M, int N, int K,
                                            const float* __restrict__ addm,
                                            int ldam) {
    const int M4 = M >> 2;
    const int Nq = N >> 2;
    for (int idx = threadIdx.x; idx < M4 * Nq; idx += 256) {
        const int mg = idx / Nq, ng = idx % Nq;
        const int m = mg * 4, n = ng * 4;
        float4 s0, s1, s2, s3;
        if (addm) {
            s0 = *reinterpret_cast<const float4*>(addm + (size_t)(m + 0) * ldam + n);
            s1 = *reinterpret_cast<const float4*>(addm + (size_t)(m + 1) * ldam + n);
            s2 = *reinterpret_cast<const float4*>(addm + (size_t)(m + 2) * ldam + n);
            s3 = *reinterpret_cast<const float4*>(addm + (size_t)(m + 3) * ldam + n);
        } else {
            s0 = s1 = s2 = s3 = make_float4(0.f, 0.f, 0.f, 0.f);
        }
        const float* a0 = A + (size_t)(m + 0) * lda;
        const float* a1 = A + (size_t)(m + 1) * lda;
        const float* a2 = A + (size_t)(m + 2) * lda;
        const float* a3 = A + (size_t)(m + 3) * lda;
        const float* b = Bm + n;
#pragma unroll 4
        for (int k = 0; k < K; ++k) {
            const float4 bv = *reinterpret_cast<const float4*>(b + (size_t)k * ldb);
            const float v0 = a0[k], v1 = a1[k], v2 = a2[k], v3 = a3[k];
            s0.x = fmaf(v0, bv.x, s0.x); s0.y = fmaf(v0, bv.y, s0.y);
            s0.z = fmaf(v0, bv.z, s0.z); s0.w = fmaf(v0, bv.w, s0.w);
            s1.x = fmaf(v1, bv.x, s1.x); s1.y = fmaf(v1, bv.y, s1.y);
            s1.z = fmaf(v1, bv.z, s1.z); s1.w = fmaf(v1, bv.w, s1.w);
            s2.x = fmaf(v2, bv.x, s2.x); s2.y = fmaf(v2, bv.y, s2.y);
            s2.z = fmaf(v2, bv.z, s2.z); s2.w = fmaf(v2, bv.w, s2.w);
            s3.x = fmaf(v3, bv.x, s3.x); s3.y = fmaf(v3, bv.y, s3.y);
            s3.z = fmaf(v3, bv.z, s3.z); s3.w = fmaf(v3, bv.w, s3.w);
        }
        *reinterpret_cast<float4*>(out + (size_t)(m + 0) * ldo + n) = s0;
        *reinterpret_cast<float4*>(out + (size_t)(m + 1) * ldo + n) = s1;
        *reinterpret_cast<float4*>(out + (size_t)(m + 2) * ldo + n) = s2;
        *reinterpret_cast<float4*>(out + (size_t)(m + 3) * ldo + n) = s3;
    }
    const int mrem0 = M4 * 4;
    for (int idx = threadIdx.x; idx < (M - mrem0) * N; idx += 256) {
        const int m = mrem0 + idx / N, n = idx % N;
        float s = addm ? addm[(size_t)m * ldam + n] : 0.f;
        const float* a = A + (size_t)m * lda;
        const float* b = Bm + n;
#pragma unroll 4
        for (int k = 0; k < K; ++k) s = fmaf(a[k], b[(size_t)k * ldb], s);
        out[(size_t)m * ldo + n] = s;
    }
}

// fold stage 1 (35 CTAs)
__global__ void __launch_bounds__(256) kernelF1(
    const float* __restrict__ We, const float* __restrict__ be,
    const float* __restrict__ Wqm, const float* __restrict__ bqm,
    const float* __restrict__ Wzp, const float* __restrict__ bzp,
    const float* __restrict__ Wd, const float* __restrict__ bd,
    const float* __restrict__ Wih) {
    const int t = blockIdx.x;
    if (t < 6) {
        const int c = t >> 1, mb = t & 1;
        small_gemmK(We + (size_t)c * 384 * EH_ + mb * 64 * EH_, EH_,
                    Wqm + (size_t)c * EH_ * L_, L_,
                    g_Weq + c * HX_ * L_ + mb * 64 * L_, L_, 64, L_, EH_,
                    nullptr, 0);
    } else if (t < 18) {
        const int u = t - 6, c = u >> 2, mb = u & 3;
        small_gemmK(We + (size_t)c * 384 * EH_ + (128 + mb * 64) * EH_, EH_,
                    Wqm + (size_t)c * EH_ * L_, L_,
                    g_Wcomb + c * H_ * L_ + mb * 64 * L_, L_, 64, L_, EH_,
                    nullptr, 0);
    } else if (t < 24) {
        const int u = t - 18, c = u >> 1, nb = u & 1;
        small_gemmK(Wzp, HZ_, Wd + (size_t)c * 384 * EH_ + nb * 64, EH_,
                    g_Wdz + c * L_ * EH_ + nb * 64, EH_, L_, 64, HZ_,
                    nullptr, 0);
    } else if (t < 28) {
        const int nb = t - 24;
        small_gemmK(Wzp, HZ_, Wih + 128 * H_ + nb * 64, H_,
                    g_Wihz + nb * 64, H_, L_, 64, HZ_, nullptr, 0);
    } else if (t < 31) {
        const int c = t - 28;
        small_gemmK(be + c * EH_, EH_, Wqm + (size_t)c * EH_ * L_, L_,
                    g_beq + c * L_, L_, 1, L_, EH_, bqm + c * L_, 0);
    } else if (t < 34) {
        const int c = t - 31;
        small_gemmK(bzp, HZ_, Wd + (size_t)c * 384 * EH_, EH_,
                    g_bdz + c * EH_, EH_, 1, EH_, HZ_, bd + c * EH_, 0);
    } else {
        small_gemmK(bzp, HZ_, Wih + 128 * H_, H_, g_bihz, H_, 1, H_, HZ_,
                    nullptr, 0);
    }
}

// fold stage 2 (108 CTAs)
__global__ void __launch_bounds__(256) kernelF2(
    const float* __restrict__ Wd, const float* __restrict__ Wpm,
    const float* __restrict__ bpm, const float* __restrict__ Whh,
    const float* __restrict__ Wih, const float* __restrict__ bih,
    const float* __restrict__ bhh) {
    const int t = blockIdx.x;
    if (t < 6) {
        const int c = t >> 1, nb = t & 1;
        small_gemmK(g_Wdz + c * L_ * EH_, EH_,
                    Wpm + (size_t)c * EH_ * F_ + nb * 64, F_,
                    g_Wzo + c * L_ * F_ + nb * 64, F_, L_, 64, EH_, nullptr, 0);
    } else if (t < 30) {
        const int u = t - 6, c = u >> 3, r = u & 7, mb = r >> 1, nb = r & 1;
        small_gemmK(Wd + (size_t)c * 384 * EH_ + (128 + mb * 64) * EH_, EH_,
                    Wpm + (size_t)c * EH_ * F_ + nb * 64, F_,
                    g_Who + c * H_ * F_ + mb * 64 * F_ + nb * 64, F_,
                    64, 64, EH_, nullptr, 0);
    } else if (t < 33) {
        const int c = t - 30;
        small_gemmK(g_bdz + c * EH_, EH_, Wpm + (size_t)c * EH_ * F_, F_,
                    g_bo + c * F_, F_, 1, F_, EH_, bpm + c * F_, 0);
    } else if (t < 81) {
        const int u = t - 33, c = u >> 4, r = u & 15, mb = r >> 2, nb = r & 3;
        small_gemmK(g_Wcomb + c * H_ * L_ + mb * 64 * L_, L_,
                    g_Wihz + nb * 64, H_,
                    g_Whh2 + (size_t)c * H_ * H_ + mb * 64 * H_ + nb * 64, H_,
                    64, 64, L_, Whh + (size_t)mb * 64 * H_ + nb * 64, H_);
    } else if (t < 105) {
        const int u = t - 81, c = u >> 3, r = u & 7, mb = r >> 2, nb = r & 3;
        small_gemmK(g_Weq + c * HX_ * L_ + mb * 64 * L_, L_,
                    g_Wihz + nb * 64, H_,
                    g_Wihq + (size_t)c * HX_ * H_ + mb * 64 * H_ + nb * 64, H_,
                    64, 64, L_, Wih + (size_t)mb * 64 * H_ + nb * 64, H_);
    } else {
        const int c = t - 105;
        for (int n = threadIdx.x; n < H_; n += 256) {
            float s = bih[n] + bhh[n] + g_bihz[n];
            for (int l = 0; l < L_; ++l)
                s = fmaf(g_beq[c * L_ + l], g_Wihz[l * H_ + n], s);
            g_bihq[c * H_ + n] = s;
        }
    }
}

// fold stage 3 (39 CTAs)
__global__ void __launch_bounds__(256) kernelF3() {
    const int t = blockIdx.x;
    if (t < 24) {
        const int c = t >> 3, r = t & 7, mb = r >> 1, nb = r & 1;
        small_gemmK(g_Wcomb + c * H_ * L_ + mb * 64 * L_, L_,
                    g_Wzo + c * L_ * F_ + nb * 64, F_,
                    g_Who2 + c * H_ * F_ + mb * 64 * F_ + nb * 64, F_,
                    64, 64, L_,
                    g_Who + c * H_ * F_ + mb * 64 * F_ + nb * 64, F_);
    } else if (t < 36) {
        const int u = t - 24, c = u >> 2, r = u & 3, mb = r >> 1, nb = r & 1;
        small_gemmK(g_Weq + c * HX_ * L_ + mb * 64 * L_, L_,
                    g_Wzo + c * L_ * F_ + nb * 64, F_,
                    g_Wxo + c * HX_ * F_ + mb * 64 * F_ + nb * 64, F_,
                    64, 64, L_, nullptr, 0);
    } else {
        const int c = t - 36;
        small_gemmK(g_beq + c * L_, L_, g_Wzo + c * L_ * F_, F_,
                    g_bo2 + c * F_, F_, 1, F_, L_, g_bo + c * F_, 0);
    }
}

// fold stage 4 (39 CTAs)
__global__ void __launch_bounds__(256) kernelF4(
    const float* __restrict__ Wx, const float* __restrict__ bx) {
    const int t = blockIdx.x;
    if (t < 24) {
        const int c = t >> 3, r = t & 7, mb = r >> 2, nb = r & 3;
        small_gemmK(Wx + (size_t)c * F_ * HX_ + mb * 64 * HX_, HX_,
                    g_Wihq + (size_t)c * HX_ * H_ + nb * 64, H_,
                    g_WxI + (size_t)c * F_ * H_ + mb * 64 * H_ + nb * 64, H_,
                    64, 64, HX_, nullptr, 0);
    } else if (t < 36) {
        const int u = t - 24, c = u >> 2, r = u & 3, mb = r >> 1, nb = r & 1;
        small_gemmK(Wx + (size_t)c * F_ * HX_ + mb * 64 * HX_, HX_,
                    g_Wxo + (size_t)c * HX_ * F_ + nb * 64, F_,
                    g_WxO + (size_t)c * F_ * F_ + mb * 64 * F_ + nb * 64, F_,
                    64, 64, HX_, nullptr, 0);
    } else {
        const int c = t - 36;
        small_gemmK(bx + c * HX_, HX_, g_Wihq + (size_t)c * HX_ * H_, H_,
                    g_bihq2 + c * H_, H_, 1, H_, HX_, g_bihq + c * H_, 0);
        small_gemmK(bx + c * HX_, HX_, g_Wxo + (size_t)c * HX_ * F_, F_,
                    g_bo3 + c * F_, F_, 1, F_, HX_, g_bo2 + c * F_, 0);
    }
}

// ===========================================================================
// Parallel GEMM machinery (kernels A and C) — packed f32x2 math.
// acc2[i][p]: p-th pair of output columns for row i (lanes = cols 2p, 2p+1).
// Same loads and accumulation order as the FFMA version -> identical results.
// ===========================================================================
__device__ __forceinline__ void gemm64(const float* __restrict__ As,
                                       const float* __restrict__ Ws,
                                       int k0, unsigned long long acc2[8][4]) {
    const int tc = threadIdx.x & 15;
    const int tr = threadIdx.x >> 4;
    const float* ap = As + tr * 8 * 128 + k0;
    const float* bp = Ws + tc * 8;
#pragma unroll 4
    for (int k = 0; k < 64; ++k) {
        const ulonglong2 b01 = *reinterpret_cast<const ulonglong2*>(bp + k * 128);
        const ulonglong2 b23 = *reinterpret_cast<const ulonglong2*>(bp + k * 128 + 4);
#pragma unroll
        for (int i = 0; i < 8; ++i) {
            const unsigned long long ai = dup2(ap[i * 128 + k]);
            FMA2(acc2[i][0], ai, b01.x, acc2[i][0]);
            FMA2(acc2[i][1], ai, b01.y, acc2[i][1]);
            FMA2(acc2[i][2], ai, b23.x, acc2[i][2]);
            FMA2(acc2[i][3], ai, b23.y, acc2[i][3]);
        }
    }
}

// Load a 128x128 fp32 tile (row stride ld) into smem
__device__ __forceinline__ void load_tile(float* dst, const float* __restrict__ src,
                                          int ld) {
    for (int idx = threadIdx.x; idx < 128 * 32; idx += 256) {
        const int r = idx >> 5;
        const int c4 = idx & 31;
        reinterpret_cast<float4*>(dst)[(r << 5) + c4] =
            *reinterpret_cast<const float4*>(src + (size_t)r * ld + (c4 << 2));
    }
}

// Load a 64x128 fp32 slab (row stride ld) into smem
__device__ __forceinline__ void load_half(float* dst, const float* __restrict__ src,
                                          int ld) {
    for (int idx = threadIdx.x; idx < 64 * 32; idx += 256) {
        const int r = idx >> 5;
        const int c4 = idx & 31;
        reinterpret_cast<float4*>(dst)[(r << 5) + c4] =
            *reinterpret_cast<const float4*>(src + (size_t)r * ld + (c4 << 2));
    }
}

__device__ __forceinline__ void zero_acc2(unsigned long long acc2[8][4]) {
#pragma unroll
    for (int i = 0; i < 8; ++i)
#pragma unroll
        for (int p = 0; p < 4; ++p) acc2[i][p] = 0ull;
}

// full 128-deep GEMM as two 64-row slabs streamed through Ws
__device__ __forceinline__ void gemm128_slabs(const float* As, float* Ws,
                                              const float* __restrict__ W,
                                              int ldw,
                                              unsigned long long acc2[8][4]) {
#pragma unroll
    for (int h = 0; h < 2; ++h) {
        load_half(Ws, W + (size_t)(h * 64) * ldw, ldw);
        __syncthreads();
        gemm64(As, Ws, h * 64, acc2);
        __syncthreads();
    }
}

// ---------------------------------------------------------------------------
// Kernel A: PO = x@WxO + bo3; PI = x@WxI + bihq2
// ---------------------------------------------------------------------------
__global__ void __launch_bounds__(256, 2) kernelA(const float* __restrict__ x) {
    extern __shared__ float sm[];
    float* As = sm;
    float* Ws = sm + 128 * 128;
    const int bt = blockIdx.x, t = blockIdx.y, c = blockIdx.z;
    const long rg0 = ((long)(c * T_ + t) * B_ + bt * 128);
    const int tc = threadIdx.x & 15, tr = threadIdx.x >> 4;

    load_tile(As, x + rg0 * F_, F_);

    unsigned long long acc2[8][4];

    // PO = x @ WxO + bo3
    zero_acc2(acc2);
    gemm128_slabs(As, Ws, g_WxO + (size_t)c * F_ * F_, F_, acc2);
#pragma unroll
    for (int i = 0; i < 8; ++i)
#pragma unroll
        for (int p = 0; p < 4; ++p) {
            const float2 f = unpack2(acc2[i][p]);
            const int n = tc * 8 + 2 * p;
            g_PO[(rg0 + tr * 8 + i) * F_ + n]     = f.x + g_bo3[c * F_ + n];
            g_PO[(rg0 + tr * 8 + i) * F_ + n + 1] = f.y + g_bo3[c * F_ + n + 1];
        }

    // PI = x @ WxI + bihq2 (two 128-col halves)
#pragma unroll
    for (int half = 0; half < 2; ++half) {
        zero_acc2(acc2);
        gemm128_slabs(As, Ws, g_WxI + (size_t)c * F_ * H_ + half * 128, H_, acc2);
#pragma unroll
        for (int i = 0; i < 8; ++i)
#pragma unroll
            for (int p = 0; p < 4; ++p) {
                const float2 f = unpack2(acc2[i][p]);
                const int n = half * 128 + tc * 8 + 2 * p;
                g_PI[(rg0 + tr * 8 + i) * H_ + n] =
                    f.x + g_bihq2[c * H_ + n];
                g_PI[(rg0 + tr * 8 + i) * H_ + n + 1] =
                    f.y + g_bihq2[c * H_ + n + 1];
            }
    }
}

// ===========================================================================
// Kernel B: R11 structure (mm4s, p0 partition in smem, scr reduce),
// arithmetic swapped to packed f32x2. Identical loads & accumulation order.
// ===========================================================================
__device__ __forceinline__ float fast_tanh(float x) {
    const float e = __expf(2.f * x);
    return 1.f - __fdividef(2.f, e + 1.f);
}

// K=256, N=256 (G=64, P=4, Ks=64); p==0 reads weights from smem copy.
// acc01[r]/acc23[r] = packed pairs of this thread's 4 output columns.
__device__ __forceinline__ void mm4s(const float* __restrict__ Wg,
                                     const float* __restrict__ Wsm,
                                     const float* __restrict__ a_s,
                                     unsigned long long acc01[RMAX_],
                                     unsigned long long acc23[RMAX_]) {
    constexpr int G = 64;   // N/4
    constexpr int Ks = 64;  // K/P
    const int g = threadIdx.x % G;
    const int p = threadIdx.x / G;
    const ulonglong2* wp = (p == 0)
        ? reinterpret_cast<const ulonglong2*>(Wsm) + g
        : reinterpret_cast<const ulonglong2*>(Wg) + (size_t)(p * Ks) * G + g;
    const float* ap = a_s + p * Ks;

    ulonglong2 w0 = wp[0 * G], w1 = wp[1 * G], w2 = wp[2 * G], w3 = wp[3 * G];
#pragma unroll 1
    for (int k = 0; k < Ks; k += 4) {
        ulonglong2 n0, n1, n2, n3;
        if (k + 4 < Ks) {
            n0 = wp[(k + 4) * G];
            n1 = wp[(k + 5) * G];
            n2 = wp[(k + 6) * G];
            n3 = wp[(k + 7) * G];
        }
#pragma unroll
        for (int r = 0; r < RMAX_; ++r) {
            const float4 a = *reinterpret_cast<const float4*>(ap + r * 256 + k);
            const unsigned long long ax = dup2(a.x);
            const unsigned long long ay = dup2(a.y);
            const unsigned long long az = dup2(a.z);
            const unsigned long long aw = dup2(a.w);
            FMA2(acc01[r], ax, w0.x, acc01[r]);
            FMA2(acc23[r], ax, w0.y, acc23[r]);
            FMA2(acc01[r], ay, w1.x, acc01[r]);
            FMA2(acc23[r], ay, w1.y, acc23[r]);
            FMA2(acc01[r], az, w2.x, acc01[r]);
            FMA2(acc23[r], az, w2.y, acc23[r]);
            FMA2(acc01[r], aw, w3.x, acc01[r]);
            FMA2(acc23[r], aw, w3.y, acc23[r]);
        }
        w0 = n0; w1 = n1; w2 = n2; w3 = n3;
    }
}

__global__ void __launch_bounds__(256, 2) kernelB(const float* __restrict__ h0) {
    // dynamic smem: hs[1536] | scr2[6144] | wsm[16384]  -> 94 KB
    extern __shared__ float smb[];
    float* hs   = smb;
    float* scr2 = smb + RMAX_ * H_;
    float* wsm  = scr2 + 4 * RMAX_ * 256;

    const int c = blockIdx.y;
    const int r0 = (blockIdx.x * (B_ - RMAX_)) / (NB_ - 1);
    const int tid = threadIdx.x;

    const float* Whh2 = g_Whh2 + (size_t)c * H_ * H_;

    for (int idx = tid; idx < RMAX_ * H_; idx += 256)
        hs[idx] = h0[(size_t)(c * B_ + r0) * H_ + idx];
    // stage rows 0..63 of Whh2 (the p=0 k-partition) into smem
    for (int idx = tid; idx < 64 * 256 / 4; idx += 256)
        reinterpret_cast<float4*>(wsm)[idx] =
            reinterpret_cast<const float4*>(Whh2)[idx];
    __syncthreads();

    unsigned long long acc01[RMAX_], acc23[RMAX_];
    const int g = tid % 64, p = tid / 64;

    long rg0 = (long)c * T_ * B_ + r0;
    for (int t = 0; t < T_; ++t, rg0 += B_) {
        // prefetch this step's PI into registers (overlaps with FMAs below)
        float pip[RMAX_];
#pragma unroll
        for (int j = 0; j < RMAX_; ++j)
            pip[j] = g_PI[rg0 * H_ + j * 256 + tid];

#pragma unroll
        for (int r = 0; r < RMAX_; ++r) { acc01[r] = 0ull; acc23[r] = 0ull; }
        mm4s(Whh2, wsm, hs, acc01, acc23);
        // store partials (same bytes as the float4 stores of R11)
#pragma unroll
        for (int r = 0; r < RMAX_; ++r) {
            ulonglong2 v; v.x = acc01[r]; v.y = acc23[r];
            *reinterpret_cast<ulonglong2*>(
                scr2 + (size_t)(p * RMAX_ + r) * 256 + 4 * g) = v;
        }
        // store Hs[t] = h (pre-update) while partials land
        for (int idx = tid; idx < RMAX_ * H_ / 4; idx += 256)
            reinterpret_cast<float4*>(&g_Hs[rg0 * H_])[idx] =
                reinterpret_cast<const float4*>(hs)[idx];
        __syncthreads();

        // reduce 4 partials + PI -> tanh -> hs (1536 outputs)
#pragma unroll
        for (int j = 0; j < RMAX_; ++j) {
            const int idx = j * 256 + tid;
            const int r = idx >> 8;
            const int n = idx & 255;
            float s = pip[j];
#pragma unroll
            for (int q = 0; q < 4; ++q)
                s += scr2[(size_t)(q * RMAX_ + r) * 256 + n];
            hs[idx] = fast_tanh(s);
        }
        __syncthreads();
    }
}

// ---------------------------------------------------------------------------
// Kernel C: out = PO + Hs@Who2
// ---------------------------------------------------------------------------
__global__ void __launch_bounds__(256, 2) kernelC(float* __restrict__ out) {
    extern __shared__ float sm[];
    float* As = sm;
    float* Ws = sm + 128 * 128;
    const int bt = blockIdx.x, t = blockIdx.y, c = blockIdx.z;
    const long rg0 = ((long)(c * T_ + t) * B_ + bt * 128);
    const int tc = threadIdx.x & 15, tr = threadIdx.x >> 4;

    unsigned long long acc2[8][4];
    zero_acc2(acc2);

    // h part: two 128-row slices of Who2 (K=256 total)
    load_tile(As, g_Hs + rg0 * H_, H_);
    gemm128_slabs(As, Ws, g_Who2 + (size_t)c * H_ * F_, F_, acc2);
    load_tile(As, g_Hs + rg0 * H_ + 128, H_);
    gemm128_slabs(As, Ws, g_Who2 + (size_t)c * H_ * F_ + 128 * F_, F_, acc2);

#pragma unroll
    for (int i = 0; i < 8; ++i)
#pragma unroll
        for (int p = 0; p < 4; ++p) {
            const float2 f = unpack2(acc2[i][p]);
            const long o = (rg0 + tr * 8 + i) * F_ + tc * 8 + 2 * p;
            out[o]     = f.x + g_PO[o];
            out[o + 1] = f.y + g_PO[o + 1];
        }
}

// ---------------------------------------------------------------------------
extern "C" void kernel_launch(void* const* d_in, const int* in_sizes, int n_in,
                              void* d_out, int out_size) {
    (void)in_sizes; (void)n_in; (void)out_size;
    const float* x        = (const float*)d_in[0];
    const float* phi_x_W  = (const float*)d_in[1];
    const float* phi_x_b  = (const float*)d_in[2];
    const float* enc_W    = (const float*)d_in[3];
    const float* enc_b    = (const float*)d_in[4];
    const float* enc_mu_W = (const float*)d_in[5];
    const float* enc_mu_b = (const float*)d_in[6];
    const float* phi_z_W  = (const float*)d_in[7];
    const float* phi_z_b  = (const float*)d_in[8];
    const float* dec_W    = (const float*)d_in[9];
    const float* dec_b    = (const float*)d_in[10];
    const float* dec_mu_W = (const float*)d_in[11];
    const float* dec_mu_b = (const float*)d_in[12];
    const float* rnn_Wih  = (const float*)d_in[13];
    const float* rnn_Whh  = (const float*)d_in[14];
    const float* rnn_bih  = (const float*)d_in[15];
    const float* rnn_bhh  = (const float*)d_in[16];
    const float* h0       = (const float*)d_in[17];
    float* out = (float*)d_out;

    const size_t smemAC = (128 * 128 + 64 * 128) * sizeof(float);  // 96 KB
    const size_t smemB  = (RMAX_ * H_ + 4 * RMAX_ * 256 + 64 * 256)
                          * sizeof(float);                          // 94 KB
    cudaFuncSetAttribute(kernelA, cudaFuncAttributeMaxDynamicSharedMemorySize,
                         (int)smemAC);
    cudaFuncSetAttribute(kernelB, cudaFuncAttributeMaxDynamicSharedMemorySize,
                         (int)smemB);
    cudaFuncSetAttribute(kernelC, cudaFuncAttributeMaxDynamicSharedMemorySize,
                         (int)smemAC);

    kernelF1<<<35, 256>>>(enc_W, enc_b, enc_mu_W, enc_mu_b, phi_z_W, phi_z_b,
                          dec_W, dec_b, rnn_Wih);
    kernelF2<<<108, 256>>>(dec_W, dec_mu_W, dec_mu_b, rnn_Whh, rnn_Wih,
                           rnn_bih, rnn_bhh);
    kernelF3<<<39, 256>>>();
    kernelF4<<<39, 256>>>(phi_x_W, phi_x_b);
    kernelA<<<dim3(4, T_, C_), 256, smemAC>>>(x);
    kernelB<<<dim3(NB_, C_), 256, smemB>>>(h0);
    kernelC<<<dim3(4, T_, C_), 256, smemAC>>>(out);
}

// round 16
// speedup vs baseline: 1.3831x; 1.0486x over previous
#include <cuda_runtime.h>
#include <math.h>

#define C_   3
#define T_   100
#define B_   512
#define F_   128
#define HX_  128
#define HZ_  128
#define H_   256
#define EH_  128
#define L_   64

#define NB_   86
#define RMAX_ 6

#define FMA2(d, a, b, c) \
    asm("fma.rn.f32x2 %0, %1, %2, %3;" : "=l"(d) : "l"(a), "l"(b), "l"(c))

__device__ __forceinline__ unsigned long long dup2(float v) {
    unsigned long long d;
    const unsigned u = __float_as_uint(v);
    asm("mov.b64 %0, {%1, %1};" : "=l"(d) : "r"(u));
    return d;
}
__device__ __forceinline__ float2 unpack2(unsigned long long v) {
    return make_float2(__uint_as_float((unsigned)v),
                       __uint_as_float((unsigned)(v >> 32)));
}

// ---- big activations scratch ----
__device__ float g_PI[(size_t)C_ * T_ * B_ * H_];
__device__ float g_PO[(size_t)C_ * T_ * B_ * F_];
__device__ float g_Hs[(size_t)C_ * T_ * B_ * H_];

// ---- folded weights ----
__device__ float g_Weq[C_ * HX_ * L_];
__device__ float g_beq[C_ * L_];
__device__ float g_Wcomb[C_ * H_ * L_];
__device__ float g_Wihz[L_ * H_];
__device__ float g_bihz[H_];
__device__ float g_Wdz[C_ * L_ * EH_];
__device__ float g_bdz[C_ * EH_];
__device__ float g_Wzo[C_ * L_ * F_];
__device__ float g_Who[C_ * H_ * F_];
__device__ float g_bo[C_ * F_];
__device__ float g_Whh2[C_ * H_ * H_];
__device__ float g_Who2[C_ * H_ * F_];
__device__ float g_WxI[C_ * F_ * H_];
__device__ float g_bihq2[C_ * H_];
__device__ float g_WxO[C_ * F_ * F_];
__device__ float g_bo3[C_ * F_];
__device__ float g_WxIa[C_ * F_ * H_];   // Wx @ Wih_x
__device__ float g_WxE[C_ * F_ * L_];    // Wx @ Weq
__device__ float g_bxi[C_ * H_];         // bx @ Wih_x
__device__ float g_bxe[C_ * L_];         // bx @ Weq

// ===========================================================================
// Fold GEMM, 64x64 output block, B-block staged in smem (Bs: K x 64, K<=128)
// ===========================================================================
__device__ __forceinline__ void gemm64f(const float* __restrict__ A, int lda,
                                        const float* __restrict__ Bm, int ldb,
                                        float* __restrict__ out, int ldo, int K,
                                        const float* __restrict__ addm, int ldam,
                                        float* Bs) {
    for (int idx = threadIdx.x; idx < K * 16; idx += 256)
        reinterpret_cast<float4*>(Bs)[idx] =
            *reinterpret_cast<const float4*>(Bm + (size_t)(idx >> 4) * ldb
                                             + (idx & 15) * 4);
    __syncthreads();
    const int m = (threadIdx.x >> 4) * 4, n = (threadIdx.x & 15) * 4;
    float4 s0, s1, s2, s3;
    if (addm) {
        s0 = *reinterpret_cast<const float4*>(addm + (size_t)(m + 0) * ldam + n);
        s1 = *reinterpret_cast<const float4*>(addm + (size_t)(m + 1) * ldam + n);
        s2 = *reinterpret_cast<const float4*>(addm + (size_t)(m + 2) * ldam + n);
        s3 = *reinterpret_cast<const float4*>(addm + (size_t)(m + 3) * ldam + n);
    } else {
        s0 = s1 = s2 = s3 = make_float4(0.f, 0.f, 0.f, 0.f);
    }
    const float* a0 = A + (size_t)(m + 0) * lda;
    const float* a1 = A + (size_t)(m + 1) * lda;
    const float* a2 = A + (size_t)(m + 2) * lda;
    const float* a3 = A + (size_t)(m + 3) * lda;
#pragma unroll 4
    for (int k = 0; k < K; ++k) {
        const float4 bv = *reinterpret_cast<const float4*>(Bs + k * 64 + n);
        const float v0 = a0[k], v1 = a1[k], v2 = a2[k], v3 = a3[k];
        s0.x = fmaf(v0, bv.x, s0.x); s0.y = fmaf(v0, bv.y, s0.y);
        s0.z = fmaf(v0, bv.z, s0.z); s0.w = fmaf(v0, bv.w, s0.w);
        s1.x = fmaf(v1, bv.x, s1.x); s1.y = fmaf(v1, bv.y, s1.y);
        s1.z = fmaf(v1, bv.z, s1.z); s1.w = fmaf(v1, bv.w, s1.w);
        s2.x = fmaf(v2, bv.x, s2.x); s2.y = fmaf(v2, bv.y, s2.y);
        s2.z = fmaf(v2, bv.z, s2.z); s2.w = fmaf(v2, bv.w, s2.w);
        s3.x = fmaf(v3, bv.x, s3.x); s3.y = fmaf(v3, bv.y, s3.y);
        s3.z = fmaf(v3, bv.z, s3.z); s3.w = fmaf(v3, bv.w, s3.w);
    }
    *reinterpret_cast<float4*>(out + (size_t)(m + 0) * ldo + n) = s0;
    *reinterpret_cast<float4*>(out + (size_t)(m + 1) * ldo + n) = s1;
    *reinterpret_cast<float4*>(out + (size_t)(m + 2) * ldo + n) = s2;
    *reinterpret_cast<float4*>(out + (size_t)(m + 3) * ldo + n) = s3;
}

// vector (M=1) fold: out[n] = a@Bm[:,n] (+ addv)
__device__ __forceinline__ void vec_gemm(const float* __restrict__ a,
                                         const float* __restrict__ Bm, int ldb,
                                         float* __restrict__ out, int N, int K,
                                         const float* __restrict__ addv) {
    for (int n = threadIdx.x; n < N; n += 256) {
        float s = addv ? addv[n] : 0.f;
#pragma unroll 4
        for (int k = 0; k < K; ++k) s = fmaf(a[k], Bm[(size_t)k * ldb + n], s);
        out[n] = s;
    }
}

// fold stage 1 (62 CTAs): raw-input products
__global__ void __launch_bounds__(256) kernelF1(
    const float* __restrict__ We, const float* __restrict__ be,
    const float* __restrict__ Wqm, const float* __restrict__ bqm,
    const float* __restrict__ Wzp, const float* __restrict__ bzp,
    const float* __restrict__ Wd, const float* __restrict__ bd,
    const float* __restrict__ Wih, const float* __restrict__ Wx,
    const float* __restrict__ bx) {
    __shared__ float Bs[128 * 64];
    const int t = blockIdx.x;
    if (t < 6) {                       // Weq = We_x@Wqm
        const int c = t >> 1, mb = t & 1;
        gemm64f(We + (size_t)c * 384 * EH_ + mb * 64 * EH_, EH_,
                Wqm + (size_t)c * EH_ * L_, L_,
                g_Weq + c * HX_ * L_ + mb * 64 * L_, L_, EH_, nullptr, 0, Bs);
    } else if (t < 18) {               // Wcomb = We_h@Wqm
        const int u = t - 6, c = u >> 2, mb = u & 3;
        gemm64f(We + (size_t)c * 384 * EH_ + (128 + mb * 64) * EH_, EH_,
                Wqm + (size_t)c * EH_ * L_, L_,
                g_Wcomb + c * H_ * L_ + mb * 64 * L_, L_, EH_, nullptr, 0, Bs);
    } else if (t < 24) {               // Wdz = Wzp@Wd_z
        const int u = t - 18, c = u >> 1, nb = u & 1;
        gemm64f(Wzp, HZ_, Wd + (size_t)c * 384 * EH_ + nb * 64, EH_,
                g_Wdz + c * L_ * EH_ + nb * 64, EH_, HZ_, nullptr, 0, Bs);
    } else if (t < 28) {               // Wihz = Wzp@Wih_z
        const int nb = t - 24;
        gemm64f(Wzp, HZ_, Wih + 128 * H_ + nb * 64, H_,
                g_Wihz + nb * 64, H_, HZ_, nullptr, 0, Bs);
    } else if (t < 52) {               // WxIa = Wx@Wih_x
        const int u = t - 28, c = u >> 3, r = u & 7, mb = r >> 2, nb = r & 3;
        gemm64f(Wx + (size_t)c * F_ * HX_ + mb * 64 * HX_, HX_,
                Wih + nb * 64, H_,
                g_WxIa + (size_t)c * F_ * H_ + mb * 64 * H_ + nb * 64, H_,
                HX_, nullptr, 0, Bs);
    } else if (t < 55) {               // beq = be@Wqm + bqm
        const int c = t - 52;
        vec_gemm(be + c * EH_, Wqm + (size_t)c * EH_ * L_, L_,
                 g_beq + c * L_, L_, EH_, bqm + c * L_);
    } else if (t < 58) {               // bdz = bzp@Wd_z + bd
        const int c = t - 55;
        vec_gemm(bzp, Wd + (size_t)c * 384 * EH_, EH_,
                 g_bdz + c * EH_, EH_, HZ_, bd + c * EH_);
    } else if (t == 58) {              // bihz = bzp@Wih_z
        vec_gemm(bzp, Wih + 128 * H_, H_, g_bihz, H_, HZ_, nullptr);
    } else {                           // bxi = bx@Wih_x
        const int c = t - 59;
        vec_gemm(bx + c * HX_, Wih, H_, g_bxi + c * H_, H_, HX_, nullptr);
    }
}

// fold stage 2 (90 CTAs): products of F1 outputs
__global__ void __launch_bounds__(256) kernelF2(
    const float* __restrict__ Wd, const float* __restrict__ Wpm,
    const float* __restrict__ bpm, const float* __restrict__ Whh,
    const float* __restrict__ Wx, const float* __restrict__ bx) {
    __shared__ float Bs[128 * 64];
    const int t = blockIdx.x;
    if (t < 6) {                       // Wzo = Wdz@Wpm
        const int c = t >> 1, nb = t & 1;
        gemm64f(g_Wdz + c * L_ * EH_, EH_,
                Wpm + (size_t)c * EH_ * F_ + nb * 64, F_,
                g_Wzo + c * L_ * F_ + nb * 64, F_, EH_, nullptr, 0, Bs);
    } else if (t < 30) {               // Who = Wd_h@Wpm
        const int u = t - 6, c = u >> 3, r = u & 7, mb = r >> 1, nb = r & 1;
        gemm64f(Wd + (size_t)c * 384 * EH_ + (128 + mb * 64) * EH_, EH_,
                Wpm + (size_t)c * EH_ * F_ + nb * 64, F_,
                g_Who + c * H_ * F_ + mb * 64 * F_ + nb * 64, F_,
                EH_, nullptr, 0, Bs);
    } else if (t < 78) {               // Whh2 = Whh + Wcomb@Wihz (K=64)
        const int u = t - 30, c = u >> 4, r = u & 15, mb = r >> 2, nb = r & 3;
        gemm64f(g_Wcomb + c * H_ * L_ + mb * 64 * L_, L_,
                g_Wihz + nb * 64, H_,
                g_Whh2 + (size_t)c * H_ * H_ + mb * 64 * H_ + nb * 64, H_,
                L_, Whh + (size_t)mb * 64 * H_ + nb * 64, H_, Bs);
    } else if (t < 84) {               // WxE = Wx@Weq
        const int u = t - 78, c = u >> 1, mb = u & 1;
        gemm64f(Wx + (size_t)c * F_ * HX_ + mb * 64 * HX_, HX_,
                g_Weq + c * HX_ * L_, L_,
                g_WxE + c * F_ * L_ + mb * 64 * L_, L_, HX_, nullptr, 0, Bs);
    } else if (t < 87) {               // bo = bdz@Wpm + bpm
        const int c = t - 84;
        vec_gemm(g_bdz + c * EH_, Wpm + (size_t)c * EH_ * F_, F_,
                 g_bo + c * F_, F_, EH_, bpm + c * F_);
    } else {                           // bxe = bx@Weq
        const int c = t - 87;
        vec_gemm(bx + c * HX_, g_Weq + c * HX_ * L_, L_,
                 g_bxe + c * L_, L_, HX_, nullptr);
    }
}

// fold stage 3 (66 CTAs): finish output/input-path folds
__global__ void __launch_bounds__(256) kernelF3(
    const float* __restrict__ bih, const float* __restrict__ bhh) {
    __shared__ float Bs[128 * 64];
    const int t = blockIdx.x;
    if (t < 24) {                      // Who2 = Who + Wcomb@Wzo (K=64)
        const int c = t >> 3, r = t & 7, mb = r >> 1, nb = r & 1;
        gemm64f(g_Wcomb + c * H_ * L_ + mb * 64 * L_, L_,
                g_Wzo + c * L_ * F_ + nb * 64, F_,
                g_Who2 + c * H_ * F_ + mb * 64 * F_ + nb * 64, F_, L_,
                g_Who + c * H_ * F_ + mb * 64 * F_ + nb * 64, F_, Bs);
    } else if (t < 36) {               // WxO = WxE@Wzo (K=64)
        const int u = t - 24, c = u >> 2, r = u & 3, mb = r >> 1, nb = r & 1;
        gemm64f(g_WxE + c * F_ * L_ + mb * 64 * L_, L_,
                g_Wzo + c * L_ * F_ + nb * 64, F_,
                g_WxO + (size_t)c * F_ * F_ + mb * 64 * F_ + nb * 64, F_,
                L_, nullptr, 0, Bs);
    } else if (t < 60) {               // WxI = WxIa + WxE@Wihz (K=64)
        const int u = t - 36, c = u >> 3, r = u & 7, mb = r >> 2, nb = r & 3;
        gemm64f(g_WxE + c * F_ * L_ + mb * 64 * L_, L_,
                g_Wihz + nb * 64, H_,
                g_WxI + (size_t)c * F_ * H_ + mb * 64 * H_ + nb * 64, H_, L_,
                g_WxIa + (size_t)c * F_ * H_ + mb * 64 * H_ + nb * 64, H_, Bs);
    } else if (t < 63) {               // bo3 = (beq+bxe)@Wzo + bo
        const int c = t - 60;
        for (int n = threadIdx.x; n < F_; n += 256) {
            float s = g_bo[c * F_ + n];
            for (int l = 0; l < L_; ++l)
                s = fmaf(g_beq[c * L_ + l] + g_bxe[c * L_ + l],
                         g_Wzo[(size_t)c * L_ * F_ + (size_t)l * F_ + n], s);
            g_bo3[c * F_ + n] = s;
        }
    } else {                           // bihq2 = bxi+bih+bhh+bihz + (beq+bxe)@Wihz
        const int c = t - 63;
        for (int n = threadIdx.x; n < H_; n += 256) {
            float s = g_bxi[c * H_ + n] + bih[n] + bhh[n] + g_bihz[n];
            for (int l = 0; l < L_; ++l)
                s = fmaf(g_beq[c * L_ + l] + g_bxe[c * L_ + l],
                         g_Wihz[l * H_ + n], s);
            g_bihq2[c * H_ + n] = s;
        }
    }
}

// ===========================================================================
// Kernels A/B/C — byte-identical to the current best (R13/R15)
// ===========================================================================
__device__ __forceinline__ void gemm64(const float* __restrict__ As,
                                       const float* __restrict__ Ws,
                                       int k0, unsigned long long acc2[8][4]) {
    const int tc = threadIdx.x & 15;
    const int tr = threadIdx.x >> 4;
    const float* ap = As + tr * 8 * 128 + k0;
    const float* bp = Ws + tc * 8;
#pragma unroll 4
    for (int k = 0; k < 64; ++k) {
        const ulonglong2 b01 = *reinterpret_cast<const ulonglong2*>(bp + k * 128);
        const ulonglong2 b23 = *reinterpret_cast<const ulonglong2*>(bp + k * 128 + 4);
#pragma unroll
        for (int i = 0; i < 8; ++i) {
            const unsigned long long ai = dup2(ap[i * 128 + k]);
            FMA2(acc2[i][0], ai, b01.x, acc2[i][0]);
            FMA2(acc2[i][1], ai, b01.y, acc2[i][1]);
            FMA2(acc2[i][2], ai, b23.x, acc2[i][2]);
            FMA2(acc2[i][3], ai, b23.y, acc2[i][3]);
        }
    }
}

__device__ __forceinline__ void load_tile(float* dst, const float* __restrict__ src,
                                          int ld) {
    for (int idx = threadIdx.x; idx < 128 * 32; idx += 256) {
        const int r = idx >> 5;
        const int c4 = idx & 31;
        reinterpret_cast<float4*>(dst)[(r << 5) + c4] =
            *reinterpret_cast<const float4*>(src + (size_t)r * ld + (c4 << 2));
    }
}

__device__ __forceinline__ void load_half(float* dst, const float* __restrict__ src,
                                          int ld) {
    for (int idx = threadIdx.x; idx < 64 * 32; idx += 256) {
        const int r = idx >> 5;
        const int c4 = idx & 31;
        reinterpret_cast<float4*>(dst)[(r << 5) + c4] =
            *reinterpret_cast<const float4*>(src + (size_t)r * ld + (c4 << 2));
    }
}

__device__ __forceinline__ void zero_acc2(unsigned long long acc2[8][4]) {
#pragma unroll
    for (int i = 0; i < 8; ++i)
#pragma unroll
        for (int p = 0; p < 4; ++p) acc2[i][p] = 0ull;
}

__device__ __forceinline__ void gemm128_slabs(const float* As, float* Ws,
                                              const float* __restrict__ W,
                                              int ldw,
                                              unsigned long long acc2[8][4]) {
#pragma unroll
    for (int h = 0; h < 2; ++h) {
        load_half(Ws, W + (size_t)(h * 64) * ldw, ldw);
        __syncthreads();
        gemm64(As, Ws, h * 64, acc2);
        __syncthreads();
    }
}

__global__ void __launch_bounds__(256, 2) kernelA(const float* __restrict__ x) {
    extern __shared__ float sm[];
    float* As = sm;
    float* Ws = sm + 128 * 128;
    const int bt = blockIdx.x, t = blockIdx.y, c = blockIdx.z;
    const long rg0 = ((long)(c * T_ + t) * B_ + bt * 128);
    const int tc = threadIdx.x & 15, tr = threadIdx.x >> 4;

    load_tile(As, x + rg0 * F_, F_);

    unsigned long long acc2[8][4];

    zero_acc2(acc2);
    gemm128_slabs(As, Ws, g_WxO + (size_t)c * F_ * F_, F_, acc2);
#pragma unroll
    for (int i = 0; i < 8; ++i)
#pragma unroll
        for (int p = 0; p < 4; ++p) {
            const float2 f = unpack2(acc2[i][p]);
            const int n = tc * 8 + 2 * p;
            g_PO[(rg0 + tr * 8 + i) * F_ + n]     = f.x + g_bo3[c * F_ + n];
            g_PO[(rg0 + tr * 8 + i) * F_ + n + 1] = f.y + g_bo3[c * F_ + n + 1];
        }

#pragma unroll
    for (int half = 0; half < 2; ++half) {
        zero_acc2(acc2);
        gemm128_slabs(As, Ws, g_WxI + (size_t)c * F_ * H_ + half * 128, H_, acc2);
#pragma unroll
        for (int i = 0; i < 8; ++i)
#pragma unroll
            for (int p = 0; p < 4; ++p) {
                const float2 f = unpack2(acc2[i][p]);
                const int n = half * 128 + tc * 8 + 2 * p;
                g_PI[(rg0 + tr * 8 + i) * H_ + n] =
                    f.x + g_bihq2[c * H_ + n];
                g_PI[(rg0 + tr * 8 + i) * H_ + n + 1] =
                    f.y + g_bihq2[c * H_ + n + 1];
            }
    }
}

__device__ __forceinline__ float fast_tanh(float x) {
    const float e = __expf(2.f * x);
    return 1.f - __fdividef(2.f, e + 1.f);
}

__device__ __forceinline__ void mm4s(const float* __restrict__ Wg,
                                     const float* __restrict__ Wsm,
                                     const float* __restrict__ a_s,
                                     unsigned long long acc01[RMAX_],
                                     unsigned long long acc23[RMAX_]) {
    constexpr int G = 64;
    constexpr int Ks = 64;
    const int g = threadIdx.x % G;
    const int p = threadIdx.x / G;
    const ulonglong2* wp = (p == 0)
        ? reinterpret_cast<const ulonglong2*>(Wsm) + g
        : reinterpret_cast<const ulonglong2*>(Wg) + (size_t)(p * Ks) * G + g;
    const float* ap = a_s + p * Ks;

    ulonglong2 w0 = wp[0 * G], w1 = wp[1 * G], w2 = wp[2 * G], w3 = wp[3 * G];
#pragma unroll 1
    for (int k = 0; k < Ks; k += 4) {
        ulonglong2 n0, n1, n2, n3;
        if (k + 4 < Ks) {
            n0 = wp[(k + 4) * G];
            n1 = wp[(k + 5) * G];
            n2 = wp[(k + 6) * G];
            n3 = wp[(k + 7) * G];
        }
#pragma unroll
        for (int r = 0; r < RMAX_; ++r) {
            const float4 a = *reinterpret_cast<const float4*>(ap + r * 256 + k);
            const unsigned long long ax = dup2(a.x);
            const unsigned long long ay = dup2(a.y);
            const unsigned long long az = dup2(a.z);
            const unsigned long long aw = dup2(a.w);
            FMA2(acc01[r], ax, w0.x, acc01[r]);
            FMA2(acc23[r], ax, w0.y, acc23[r]);
            FMA2(acc01[r], ay, w1.x, acc01[r]);
            FMA2(acc23[r], ay, w1.y, acc23[r]);
            FMA2(acc01[r], az, w2.x, acc01[r]);
            FMA2(acc23[r], az, w2.y, acc23[r]);
            FMA2(acc01[r], aw, w3.x, acc01[r]);
            FMA2(acc23[r], aw, w3.y, acc23[r]);
        }
        w0 = n0; w1 = n1; w2 = n2; w3 = n3;
    }
}

__global__ void __launch_bounds__(256, 2) kernelB(const float* __restrict__ h0) {
    extern __shared__ float smb[];
    float* hs   = smb;
    float* scr2 = smb + RMAX_ * H_;
    float* wsm  = scr2 + 4 * RMAX_ * 256;

    const int c = blockIdx.y;
    const int r0 = (blockIdx.x * (B_ - RMAX_)) / (NB_ - 1);
    const int tid = threadIdx.x;

    const float* Whh2 = g_Whh2 + (size_t)c * H_ * H_;

    for (int idx = tid; idx < RMAX_ * H_; idx += 256)
        hs[idx] = h0[(size_t)(c * B_ + r0) * H_ + idx];
    for (int idx = tid; idx < 64 * 256 / 4; idx += 256)
        reinterpret_cast<float4*>(wsm)[idx] =
            reinterpret_cast<const float4*>(Whh2)[idx];
    __syncthreads();

    unsigned long long acc01[RMAX_], acc23[RMAX_];
    const int g = tid % 64, p = tid / 64;

    long rg0 = (long)c * T_ * B_ + r0;
    for (int t = 0; t < T_; ++t, rg0 += B_) {
        float pip[RMAX_];
#pragma unroll
        for (int j = 0; j < RMAX_; ++j)
            pip[j] = g_PI[rg0 * H_ + j * 256 + tid];

#pragma unroll
        for (int r = 0; r < RMAX_; ++r) { acc01[r] = 0ull; acc23[r] = 0ull; }
        mm4s(Whh2, wsm, hs, acc01, acc23);
#pragma unroll
        for (int r = 0; r < RMAX_; ++r) {
            ulonglong2 v; v.x = acc01[r]; v.y = acc23[r];
            *reinterpret_cast<ulonglong2*>(
                scr2 + (size_t)(p * RMAX_ + r) * 256 + 4 * g) = v;
        }
        for (int idx = tid; idx < RMAX_ * H_ / 4; idx += 256)
            reinterpret_cast<float4*>(&g_Hs[rg0 * H_])[idx] =
                reinterpret_cast<const float4*>(hs)[idx];
        __syncthreads();

#pragma unroll
        for (int j = 0; j < RMAX_; ++j) {
            const int idx = j * 256 + tid;
            const int r = idx >> 8;
            const int n = idx & 255;
            float s = pip[j];
#pragma unroll
            for (int q = 0; q < 4; ++q)
                s += scr2[(size_t)(q * RMAX_ + r) * 256 + n];
            hs[idx] = fast_tanh(s);
        }
        __syncthreads();
    }
}

__global__ void __launch_bounds__(256, 2) kernelC(float* __restrict__ out) {
    extern __shared__ float sm[];
    float* As = sm;
    float* Ws = sm + 128 * 128;
    const int bt = blockIdx.x, t = blockIdx.y, c = blockIdx.z;
    const long rg0 = ((long)(c * T_ + t) * B_ + bt * 128);
    const int tc = threadIdx.x & 15, tr = threadIdx.x >> 4;

    unsigned long long acc2[8][4];
    zero_acc2(acc2);

    load_tile(As, g_Hs + rg0 * H_, H_);
    gemm128_slabs(As, Ws, g_Who2 + (size_t)c * H_ * F_, F_, acc2);
    load_tile(As, g_Hs + rg0 * H_ + 128, H_);
    gemm128_slabs(As, Ws, g_Who2 + (size_t)c * H_ * F_ + 128 * F_, F_, acc2);

#pragma unroll
    for (int i = 0; i < 8; ++i)
#pragma unroll
        for (int p = 0; p < 4; ++p) {
            const float2 f = unpack2(acc2[i][p]);
            const long o = (rg0 + tr * 8 + i) * F_ + tc * 8 + 2 * p;
            out[o]     = f.x + g_PO[o];
            out[o + 1] = f.y + g_PO[o + 1];
        }
}

// ---------------------------------------------------------------------------
extern "C" void kernel_launch(void* const* d_in, const int* in_sizes, int n_in,
                              void* d_out, int out_size) {
    (void)in_sizes; (void)n_in; (void)out_size;
    const float* x        = (const float*)d_in[0];
    const float* phi_x_W  = (const float*)d_in[1];
    const float* phi_x_b  = (const float*)d_in[2];
    const float* enc_W    = (const float*)d_in[3];
    const float* enc_b    = (const float*)d_in[4];
    const float* enc_mu_W = (const float*)d_in[5];
    const float* enc_mu_b = (const float*)d_in[6];
    const float* phi_z_W  = (const float*)d_in[7];
    const float* phi_z_b  = (const float*)d_in[8];
    const float* dec_W    = (const float*)d_in[9];
    const float* dec_b    = (const float*)d_in[10];
    const float* dec_mu_W = (const float*)d_in[11];
    const float* dec_mu_b = (const float*)d_in[12];
    const float* rnn_Wih  = (const float*)d_in[13];
    const float* rnn_Whh  = (const float*)d_in[14];
    const float* rnn_bih  = (const float*)d_in[15];
    const float* rnn_bhh  = (const float*)d_in[16];
    const float* h0       = (const float*)d_in[17];
    float* out = (float*)d_out;

    const size_t smemAC = (128 * 128 + 64 * 128) * sizeof(float);  // 96 KB
    const size_t smemB  = (RMAX_ * H_ + 4 * RMAX_ * 256 + 64 * 256)
                          * sizeof(float);                          // 94 KB
    cudaFuncSetAttribute(kernelA, cudaFuncAttributeMaxDynamicSharedMemorySize,
                         (int)smemAC);
    cudaFuncSetAttribute(kernelB, cudaFuncAttributeMaxDynamicSharedMemorySize,
                         (int)smemB);
    cudaFuncSetAttribute(kernelC, cudaFuncAttributeMaxDynamicSharedMemorySize,
                         (int)smemAC);

    kernelF1<<<62, 256>>>(enc_W, enc_b, enc_mu_W, enc_mu_b, phi_z_W, phi_z_b,
                          dec_W, dec_b, rnn_Wih, phi_x_W, phi_x_b);
    kernelF2<<<90, 256>>>(dec_W, dec_mu_W, dec_mu_b, rnn_Whh, phi_x_W, phi_x_b);
    kernelF3<<<66, 256>>>(rnn_bih, rnn_bhh);
    kernelA<<<dim3(4, T_, C_), 256, smemAC>>>(x);
    kernelB<<<dim3(NB_, C_), 256, smemB>>>(h0);
    kernelC<<<dim3(4, T_, C_), 256, smemAC>>>(out);
}

// round 17
// speedup vs baseline: 1.4014x; 1.0132x over previous
#include <cuda_runtime.h>
#include <math.h>

#define C_   3
#define T_   100
#define B_   512
#define F_   128
#define HX_  128
#define HZ_  128
#define H_   256
#define EH_  128
#define L_   64

#define NB_   86
#define RMAX_ 6

#define FMA2(d, a, b, c) \
    asm("fma.rn.f32x2 %0, %1, %2, %3;" : "=l"(d) : "l"(a), "l"(b), "l"(c))

__device__ __forceinline__ unsigned long long dup2(float v) {
    unsigned long long d;
    const unsigned u = __float_as_uint(v);
    asm("mov.b64 %0, {%1, %1};" : "=l"(d) : "r"(u));
    return d;
}
__device__ __forceinline__ float2 unpack2(unsigned long long v) {
    return make_float2(__uint_as_float((unsigned)v),
                       __uint_as_float((unsigned)(v >> 32)));
}

// ---- big activations scratch ----
__device__ float g_PI[(size_t)C_ * T_ * B_ * H_];
__device__ float g_PO[(size_t)C_ * T_ * B_ * F_];
__device__ float g_Hs[(size_t)C_ * T_ * B_ * H_];

// ---- folded weights ----
__device__ float g_Weq[C_ * HX_ * L_];
__device__ float g_beq[C_ * L_];
__device__ float g_Wcomb[C_ * H_ * L_];
__device__ float g_Wihz[L_ * H_];
__device__ float g_bihz[H_];
__device__ float g_Wdz[C_ * L_ * EH_];
__device__ float g_bdz[C_ * EH_];
__device__ float g_Wzo[C_ * L_ * F_];
__device__ float g_Who[C_ * H_ * F_];
__device__ float g_bo[C_ * F_];
__device__ float g_Whh2[C_ * H_ * H_];
__device__ float g_Who2[C_ * H_ * F_];
__device__ float g_WxI[C_ * F_ * H_];
__device__ float g_bihq2[C_ * H_];
__device__ float g_WxO[C_ * F_ * F_];
__device__ float g_bo3[C_ * F_];
__device__ float g_WxIa[C_ * F_ * H_];   // Wx @ Wih_x
__device__ float g_WxE[C_ * F_ * L_];    // Wx @ Weq
__device__ float g_bxi[C_ * H_];         // bx @ Wih_x
__device__ float g_bxe[C_ * L_];         // bx @ Weq

// ===========================================================================
// Fold GEMM, 64x64 output block, B-block staged in smem (Bs: K x 64, K<=128)
// ===========================================================================
__device__ __forceinline__ void gemm64f(const float* __restrict__ A, int lda,
                                        const float* __restrict__ Bm, int ldb,
                                        float* __restrict__ out, int ldo, int K,
                                        const float* __restrict__ addm, int ldam,
                                        float* Bs) {
    for (int idx = threadIdx.x; idx < K * 16; idx += 256)
        reinterpret_cast<float4*>(Bs)[idx] =
            *reinterpret_cast<const float4*>(Bm + (size_t)(idx >> 4) * ldb
                                             + (idx & 15) * 4);
    __syncthreads();
    const int m = (threadIdx.x >> 4) * 4, n = (threadIdx.x & 15) * 4;
    float4 s0, s1, s2, s3;
    if (addm) {
        s0 = *reinterpret_cast<const float4*>(addm + (size_t)(m + 0) * ldam + n);
        s1 = *reinterpret_cast<const float4*>(addm + (size_t)(m + 1) * ldam + n);
        s2 = *reinterpret_cast<const float4*>(addm + (size_t)(m + 2) * ldam + n);
        s3 = *reinterpret_cast<const float4*>(addm + (size_t)(m + 3) * ldam + n);
    } else {
        s0 = s1 = s2 = s3 = make_float4(0.f, 0.f, 0.f, 0.f);
    }
    const float* a0 = A + (size_t)(m + 0) * lda;
    const float* a1 = A + (size_t)(m + 1) * lda;
    const float* a2 = A + (size_t)(m + 2) * lda;
    const float* a3 = A + (size_t)(m + 3) * lda;
#pragma unroll 4
    for (int k = 0; k < K; ++k) {
        const float4 bv = *reinterpret_cast<const float4*>(Bs + k * 64 + n);
        const float v0 = a0[k], v1 = a1[k], v2 = a2[k], v3 = a3[k];
        s0.x = fmaf(v0, bv.x, s0.x); s0.y = fmaf(v0, bv.y, s0.y);
        s0.z = fmaf(v0, bv.z, s0.z); s0.w = fmaf(v0, bv.w, s0.w);
        s1.x = fmaf(v1, bv.x, s1.x); s1.y = fmaf(v1, bv.y, s1.y);
        s1.z = fmaf(v1, bv.z, s1.z); s1.w = fmaf(v1, bv.w, s1.w);
        s2.x = fmaf(v2, bv.x, s2.x); s2.y = fmaf(v2, bv.y, s2.y);
        s2.z = fmaf(v2, bv.z, s2.z); s2.w = fmaf(v2, bv.w, s2.w);
        s3.x = fmaf(v3, bv.x, s3.x); s3.y = fmaf(v3, bv.y, s3.y);
        s3.z = fmaf(v3, bv.z, s3.z); s3.w = fmaf(v3, bv.w, s3.w);
    }
    *reinterpret_cast<float4*>(out + (size_t)(m + 0) * ldo + n) = s0;
    *reinterpret_cast<float4*>(out + (size_t)(m + 1) * ldo + n) = s1;
    *reinterpret_cast<float4*>(out + (size_t)(m + 2) * ldo + n) = s2;
    *reinterpret_cast<float4*>(out + (size_t)(m + 3) * ldo + n) = s3;
}

// vector (M=1) fold: out[n] = a@Bm[:,n] (+ addv)
__device__ __forceinline__ void vec_gemm(const float* __restrict__ a,
                                         const float* __restrict__ Bm, int ldb,
                                         float* __restrict__ out, int N, int K,
                                         const float* __restrict__ addv) {
    for (int n = threadIdx.x; n < N; n += 256) {
        float s = addv ? addv[n] : 0.f;
#pragma unroll 4
        for (int k = 0; k < K; ++k) s = fmaf(a[k], Bm[(size_t)k * ldb + n], s);
        out[n] = s;
    }
}

// fold stage 1 (62 CTAs)
__global__ void __launch_bounds__(256) kernelF1(
    const float* __restrict__ We, const float* __restrict__ be,
    const float* __restrict__ Wqm, const float* __restrict__ bqm,
    const float* __restrict__ Wzp, const float* __restrict__ bzp,
    const float* __restrict__ Wd, const float* __restrict__ bd,
    const float* __restrict__ Wih, const float* __restrict__ Wx,
    const float* __restrict__ bx) {
    __shared__ float Bs[128 * 64];
    const int t = blockIdx.x;
    if (t < 6) {
        const int c = t >> 1, mb = t & 1;
        gemm64f(We + (size_t)c * 384 * EH_ + mb * 64 * EH_, EH_,
                Wqm + (size_t)c * EH_ * L_, L_,
                g_Weq + c * HX_ * L_ + mb * 64 * L_, L_, EH_, nullptr, 0, Bs);
    } else if (t < 18) {
        const int u = t - 6, c = u >> 2, mb = u & 3;
        gemm64f(We + (size_t)c * 384 * EH_ + (128 + mb * 64) * EH_, EH_,
                Wqm + (size_t)c * EH_ * L_, L_,
                g_Wcomb + c * H_ * L_ + mb * 64 * L_, L_, EH_, nullptr, 0, Bs);
    } else if (t < 24) {
        const int u = t - 18, c = u >> 1, nb = u & 1;
        gemm64f(Wzp, HZ_, Wd + (size_t)c * 384 * EH_ + nb * 64, EH_,
                g_Wdz + c * L_ * EH_ + nb * 64, EH_, HZ_, nullptr, 0, Bs);
    } else if (t < 28) {
        const int nb = t - 24;
        gemm64f(Wzp, HZ_, Wih + 128 * H_ + nb * 64, H_,
                g_Wihz + nb * 64, H_, HZ_, nullptr, 0, Bs);
    } else if (t < 52) {
        const int u = t - 28, c = u >> 3, r = u & 7, mb = r >> 2, nb = r & 3;
        gemm64f(Wx + (size_t)c * F_ * HX_ + mb * 64 * HX_, HX_,
                Wih + nb * 64, H_,
                g_WxIa + (size_t)c * F_ * H_ + mb * 64 * H_ + nb * 64, H_,
                HX_, nullptr, 0, Bs);
    } else if (t < 55) {
        const int c = t - 52;
        vec_gemm(be + c * EH_, Wqm + (size_t)c * EH_ * L_, L_,
                 g_beq + c * L_, L_, EH_, bqm + c * L_);
    } else if (t < 58) {
        const int c = t - 55;
        vec_gemm(bzp, Wd + (size_t)c * 384 * EH_, EH_,
                 g_bdz + c * EH_, EH_, HZ_, bd + c * EH_);
    } else if (t == 58) {
        vec_gemm(bzp, Wih + 128 * H_, H_, g_bihz, H_, HZ_, nullptr);
    } else {
        const int c = t - 59;
        vec_gemm(bx + c * HX_, Wih, H_, g_bxi + c * H_, H_, HX_, nullptr);
    }
}

// fold stage 2 (90 CTAs)
__global__ void __launch_bounds__(256) kernelF2(
    const float* __restrict__ Wd, const float* __restrict__ Wpm,
    const float* __restrict__ bpm, const float* __restrict__ Whh,
    const float* __restrict__ Wx, const float* __restrict__ bx) {
    __shared__ float Bs[128 * 64];
    const int t = blockIdx.x;
    if (t < 6) {
        const int c = t >> 1, nb = t & 1;
        gemm64f(g_Wdz + c * L_ * EH_, EH_,
                Wpm + (size_t)c * EH_ * F_ + nb * 64, F_,
                g_Wzo + c * L_ * F_ + nb * 64, F_, EH_, nullptr, 0, Bs);
    } else if (t < 30) {
        const int u = t - 6, c = u >> 3, r = u & 7, mb = r >> 1, nb = r & 1;
        gemm64f(Wd + (size_t)c * 384 * EH_ + (128 + mb * 64) * EH_, EH_,
                Wpm + (size_t)c * EH_ * F_ + nb * 64, F_,
                g_Who + c * H_ * F_ + mb * 64 * F_ + nb * 64, F_,
                EH_, nullptr, 0, Bs);
    } else if (t < 78) {
        const int u = t - 30, c = u >> 4, r = u & 15, mb = r >> 2, nb = r & 3;
        gemm64f(g_Wcomb + c * H_ * L_ + mb * 64 * L_, L_,
                g_Wihz + nb * 64, H_,
                g_Whh2 + (size_t)c * H_ * H_ + mb * 64 * H_ + nb * 64, H_,
                L_, Whh + (size_t)mb * 64 * H_ + nb * 64, H_, Bs);
    } else if (t < 84) {
        const int u = t - 78, c = u >> 1, mb = u & 1;
        gemm64f(Wx + (size_t)c * F_ * HX_ + mb * 64 * HX_, HX_,
                g_Weq + c * HX_ * L_, L_,
                g_WxE + c * F_ * L_ + mb * 64 * L_, L_, HX_, nullptr, 0, Bs);
    } else if (t < 87) {
        const int c = t - 84;
        vec_gemm(g_bdz + c * EH_, Wpm + (size_t)c * EH_ * F_, F_,
                 g_bo + c * F_, F_, EH_, bpm + c * F_);
    } else {
        const int c = t - 87;
        vec_gemm(bx + c * HX_, g_Weq + c * HX_ * L_, L_,
                 g_bxe + c * L_, L_, HX_, nullptr);
    }
}

// fold stage 3 (66 CTAs)
__global__ void __launch_bounds__(256) kernelF3(
    const float* __restrict__ bih, const float* __restrict__ bhh) {
    __shared__ float Bs[128 * 64];
    const int t = blockIdx.x;
    if (t < 24) {
        const int c = t >> 3, r = t & 7, mb = r >> 1, nb = r & 1;
        gemm64f(g_Wcomb + c * H_ * L_ + mb * 64 * L_, L_,
                g_Wzo + c * L_ * F_ + nb * 64, F_,
                g_Who2 + c * H_ * F_ + mb * 64 * F_ + nb * 64, F_, L_,
                g_Who + c * H_ * F_ + mb * 64 * F_ + nb * 64, F_, Bs);
    } else if (t < 36) {
        const int u = t - 24, c = u >> 2, r = u & 3, mb = r >> 1, nb = r & 1;
        gemm64f(g_WxE + c * F_ * L_ + mb * 64 * L_, L_,
                g_Wzo + c * L_ * F_ + nb * 64, F_,
                g_WxO + (size_t)c * F_ * F_ + mb * 64 * F_ + nb * 64, F_,
                L_, nullptr, 0, Bs);
    } else if (t < 60) {
        const int u = t - 36, c = u >> 3, r = u & 7, mb = r >> 2, nb = r & 3;
        gemm64f(g_WxE + c * F_ * L_ + mb * 64 * L_, L_,
                g_Wihz + nb * 64, H_,
                g_WxI + (size_t)c * F_ * H_ + mb * 64 * H_ + nb * 64, H_, L_,
                g_WxIa + (size_t)c * F_ * H_ + mb * 64 * H_ + nb * 64, H_, Bs);
    } else if (t < 63) {
        const int c = t - 60;
        for (int n = threadIdx.x; n < F_; n += 256) {
            float s = g_bo[c * F_ + n];
            for (int l = 0; l < L_; ++l)
                s = fmaf(g_beq[c * L_ + l] + g_bxe[c * L_ + l],
                         g_Wzo[(size_t)c * L_ * F_ + (size_t)l * F_ + n], s);
            g_bo3[c * F_ + n] = s;
        }
    } else {
        const int c = t - 63;
        for (int n = threadIdx.x; n < H_; n += 256) {
            float s = g_bxi[c * H_ + n] + bih[n] + bhh[n] + g_bihz[n];
            for (int l = 0; l < L_; ++l)
                s = fmaf(g_beq[c * L_ + l] + g_bxe[c * L_ + l],
                         g_Wihz[l * H_ + n], s);
            g_bihq2[c * H_ + n] = s;
        }
    }
}

// ===========================================================================
// Parallel GEMM (A and C): k-chunked float4 a-loads (2x fewer LDS wavefronts),
// same accumulation order over k -> bit-identical results.
// ===========================================================================
__device__ __forceinline__ void gemm64(const float* __restrict__ As,
                                       const float* __restrict__ Ws,
                                       int k0, unsigned long long acc2[8][4]) {
    const int tc = threadIdx.x & 15;
    const int tr = threadIdx.x >> 4;
    const float* ap = As + tr * 8 * 128 + k0;
    const float* bp = Ws + tc * 8;
#pragma unroll 2
    for (int k4 = 0; k4 < 64; k4 += 4) {
        float4 av[8];
#pragma unroll
        for (int i = 0; i < 8; ++i)
            av[i] = *reinterpret_cast<const float4*>(ap + i * 128 + k4);
#pragma unroll
        for (int kk = 0; kk < 4; ++kk) {
            const int k = k4 + kk;
            const ulonglong2 b01 =
                *reinterpret_cast<const ulonglong2*>(bp + k * 128);
            const ulonglong2 b23 =
                *reinterpret_cast<const ulonglong2*>(bp + k * 128 + 4);
#pragma unroll
            for (int i = 0; i < 8; ++i) {
                const float a = (kk == 0) ? av[i].x : (kk == 1) ? av[i].y
                              : (kk == 2) ? av[i].z : av[i].w;
                const unsigned long long ai = dup2(a);
                FMA2(acc2[i][0], ai, b01.x, acc2[i][0]);
                FMA2(acc2[i][1], ai, b01.y, acc2[i][1]);
                FMA2(acc2[i][2], ai, b23.x, acc2[i][2]);
                FMA2(acc2[i][3], ai, b23.y, acc2[i][3]);
            }
        }
    }
}

__device__ __forceinline__ void load_tile(float* dst, const float* __restrict__ src,
                                          int ld) {
    for (int idx = threadIdx.x; idx < 128 * 32; idx += 256) {
        const int r = idx >> 5;
        const int c4 = idx & 31;
        reinterpret_cast<float4*>(dst)[(r << 5) + c4] =
            *reinterpret_cast<const float4*>(src + (size_t)r * ld + (c4 << 2));
    }
}

__device__ __forceinline__ void load_half(float* dst, const float* __restrict__ src,
                                          int ld) {
    for (int idx = threadIdx.x; idx < 64 * 32; idx += 256) {
        const int r = idx >> 5;
        const int c4 = idx & 31;
        reinterpret_cast<float4*>(dst)[(r << 5) + c4] =
            *reinterpret_cast<const float4*>(src + (size_t)r * ld + (c4 << 2));
    }
}

__device__ __forceinline__ void zero_acc2(unsigned long long acc2[8][4]) {
#pragma unroll
    for (int i = 0; i < 8; ++i)
#pragma unroll
        for (int p = 0; p < 4; ++p) acc2[i][p] = 0ull;
}

__device__ __forceinline__ void gemm128_slabs(const float* As, float* Ws,
                                              const float* __restrict__ W,
                                              int ldw,
                                              unsigned long long acc2[8][4]) {
#pragma unroll
    for (int h = 0; h < 2; ++h) {
        load_half(Ws, W + (size_t)(h * 64) * ldw, ldw);
        __syncthreads();
        gemm64(As, Ws, h * 64, acc2);
        __syncthreads();
    }
}

__global__ void __launch_bounds__(256, 2) kernelA(const float* __restrict__ x) {
    extern __shared__ float sm[];
    float* As = sm;
    float* Ws = sm + 128 * 128;
    const int bt = blockIdx.x, t = blockIdx.y, c = blockIdx.z;
    const long rg0 = ((long)(c * T_ + t) * B_ + bt * 128);
    const int tc = threadIdx.x & 15, tr = threadIdx.x >> 4;

    load_tile(As, x + rg0 * F_, F_);

    unsigned long long acc2[8][4];

    zero_acc2(acc2);
    gemm128_slabs(As, Ws, g_WxO + (size_t)c * F_ * F_, F_, acc2);
#pragma unroll
    for (int i = 0; i < 8; ++i)
#pragma unroll
        for (int p = 0; p < 4; ++p) {
            const float2 f = unpack2(acc2[i][p]);
            const int n = tc * 8 + 2 * p;
            g_PO[(rg0 + tr * 8 + i) * F_ + n]     = f.x + g_bo3[c * F_ + n];
            g_PO[(rg0 + tr * 8 + i) * F_ + n + 1] = f.y + g_bo3[c * F_ + n + 1];
        }

#pragma unroll
    for (int half = 0; half < 2; ++half) {
        zero_acc2(acc2);
        gemm128_slabs(As, Ws, g_WxI + (size_t)c * F_ * H_ + half * 128, H_, acc2);
#pragma unroll
        for (int i = 0; i < 8; ++i)
#pragma unroll
            for (int p = 0; p < 4; ++p) {
                const float2 f = unpack2(acc2[i][p]);
                const int n = half * 128 + tc * 8 + 2 * p;
                g_PI[(rg0 + tr * 8 + i) * H_ + n] =
                    f.x + g_bihq2[c * H_ + n];
                g_PI[(rg0 + tr * 8 + i) * H_ + n + 1] =
                    f.y + g_bihq2[c * H_ + n + 1];
            }
    }
}

// ===========================================================================
// Kernel B — unchanged
// ===========================================================================
__device__ __forceinline__ float fast_tanh(float x) {
    const float e = __expf(2.f * x);
    return 1.f - __fdividef(2.f, e + 1.f);
}

__device__ __forceinline__ void mm4s(const float* __restrict__ Wg,
                                     const float* __restrict__ Wsm,
                                     const float* __restrict__ a_s,
                                     unsigned long long acc01[RMAX_],
                                     unsigned long long acc23[RMAX_]) {
    constexpr int G = 64;
    constexpr int Ks = 64;
    const int g = threadIdx.x % G;
    const int p = threadIdx.x / G;
    const ulonglong2* wp = (p == 0)
        ? reinterpret_cast<const ulonglong2*>(Wsm) + g
        : reinterpret_cast<const ulonglong2*>(Wg) + (size_t)(p * Ks) * G + g;
    const float* ap = a_s + p * Ks;

    ulonglong2 w0 = wp[0 * G], w1 = wp[1 * G], w2 = wp[2 * G], w3 = wp[3 * G];
#pragma unroll 1
    for (int k = 0; k < Ks; k += 4) {
        ulonglong2 n0, n1, n2, n3;
        if (k + 4 < Ks) {
            n0 = wp[(k + 4) * G];
            n1 = wp[(k + 5) * G];
            n2 = wp[(k + 6) * G];
            n3 = wp[(k + 7) * G];
        }
#pragma unroll
        for (int r = 0; r < RMAX_; ++r) {
            const float4 a = *reinterpret_cast<const float4*>(ap + r * 256 + k);
            const unsigned long long ax = dup2(a.x);
            const unsigned long long ay = dup2(a.y);
            const unsigned long long az = dup2(a.z);
            const unsigned long long aw = dup2(a.w);
            FMA2(acc01[r], ax, w0.x, acc01[r]);
            FMA2(acc23[r], ax, w0.y, acc23[r]);
            FMA2(acc01[r], ay, w1.x, acc01[r]);
            FMA2(acc23[r], ay, w1.y, acc23[r]);
            FMA2(acc01[r], az, w2.x, acc01[r]);
            FMA2(acc23[r], az, w2.y, acc23[r]);
            FMA2(acc01[r], aw, w3.x, acc01[r]);
            FMA2(acc23[r], aw, w3.y, acc23[r]);
        }
        w0 = n0; w1 = n1; w2 = n2; w3 = n3;
    }
}

__global__ void __launch_bounds__(256, 2) kernelB(const float* __restrict__ h0) {
    extern __shared__ float smb[];
    float* hs   = smb;
    float* scr2 = smb + RMAX_ * H_;
    float* wsm  = scr2 + 4 * RMAX_ * 256;

    const int c = blockIdx.y;
    const int r0 = (blockIdx.x * (B_ - RMAX_)) / (NB_ - 1);
    const int tid = threadIdx.x;

    const float* Whh2 = g_Whh2 + (size_t)c * H_ * H_;

    for (int idx = tid; idx < RMAX_ * H_; idx += 256)
        hs[idx] = h0[(size_t)(c * B_ + r0) * H_ + idx];
    for (int idx = tid; idx < 64 * 256 / 4; idx += 256)
        reinterpret_cast<float4*>(wsm)[idx] =
            reinterpret_cast<const float4*>(Whh2)[idx];
    __syncthreads();

    unsigned long long acc01[RMAX_], acc23[RMAX_];
    const int g = tid % 64, p = tid / 64;

    long rg0 = (long)c * T_ * B_ + r0;
    for (int t = 0; t < T_; ++t, rg0 += B_) {
        float pip[RMAX_];
#pragma unroll
        for (int j = 0; j < RMAX_; ++j)
            pip[j] = g_PI[rg0 * H_ + j * 256 + tid];

#pragma unroll
        for (int r = 0; r < RMAX_; ++r) { acc01[r] = 0ull; acc23[r] = 0ull; }
        mm4s(Whh2, wsm, hs, acc01, acc23);
#pragma unroll
        for (int r = 0; r < RMAX_; ++r) {
            ulonglong2 v; v.x = acc01[r]; v.y = acc23[r];
            *reinterpret_cast<ulonglong2*>(
                scr2 + (size_t)(p * RMAX_ + r) * 256 + 4 * g) = v;
        }
        for (int idx = tid; idx < RMAX_ * H_ / 4; idx += 256)
            reinterpret_cast<float4*>(&g_Hs[rg0 * H_])[idx] =
                reinterpret_cast<const float4*>(hs)[idx];
        __syncthreads();

#pragma unroll
        for (int j = 0; j < RMAX_; ++j) {
            const int idx = j * 256 + tid;
            const int r = idx >> 8;
            const int n = idx & 255;
            float s = pip[j];
#pragma unroll
            for (int q = 0; q < 4; ++q)
                s += scr2[(size_t)(q * RMAX_ + r) * 256 + n];
            hs[idx] = fast_tanh(s);
        }
        __syncthreads();
    }
}

__global__ void __launch_bounds__(256, 2) kernelC(float* __restrict__ out) {
    extern __shared__ float sm[];
    float* As = sm;
    float* Ws = sm + 128 * 128;
    const int bt = blockIdx.x, t = blockIdx.y, c = blockIdx.z;
    const long rg0 = ((long)(c * T_ + t) * B_ + bt * 128);
    const int tc = threadIdx.x & 15, tr = threadIdx.x >> 4;

    unsigned long long acc2[8][4];
    zero_acc2(acc2);

    load_tile(As, g_Hs + rg0 * H_, H_);
    gemm128_slabs(As, Ws, g_Who2 + (size_t)c * H_ * F_, F_, acc2);
    load_tile(As, g_Hs + rg0 * H_ + 128, H_);
    gemm128_slabs(As, Ws, g_Who2 + (size_t)c * H_ * F_ + 128 * F_, F_, acc2);

#pragma unroll
    for (int i = 0; i < 8; ++i)
#pragma unroll
        for (int p = 0; p < 4; ++p) {
            const float2 f = unpack2(acc2[i][p]);
            const long o = (rg0 + tr * 8 + i) * F_ + tc * 8 + 2 * p;
            out[o]     = f.x + g_PO[o];
            out[o + 1] = f.y + g_PO[o + 1];
        }
}

// ---------------------------------------------------------------------------
extern "C" void kernel_launch(void* const* d_in, const int* in_sizes, int n_in,
                              void* d_out, int out_size) {
    (void)in_sizes; (void)n_in; (void)out_size;
    const float* x        = (const float*)d_in[0];
    const float* phi_x_W  = (const float*)d_in[1];
    const float* phi_x_b  = (const float*)d_in[2];
    const float* enc_W    = (const float*)d_in[3];
    const float* enc_b    = (const float*)d_in[4];
    const float* enc_mu_W = (const float*)d_in[5];
    const float* enc_mu_b = (const float*)d_in[6];
    const float* phi_z_W  = (const float*)d_in[7];
    const float* phi_z_b  = (const float*)d_in[8];
    const float* dec_W    = (const float*)d_in[9];
    const float* dec_b    = (const float*)d_in[10];
    const float* dec_mu_W = (const float*)d_in[11];
    const float* dec_mu_b = (const float*)d_in[12];
    const float* rnn_Wih  = (const float*)d_in[13];
    const float* rnn_Whh  = (const float*)d_in[14];
    const float* rnn_bih  = (const float*)d_in[15];
    const float* rnn_bhh  = (const float*)d_in[16];
    const float* h0       = (const float*)d_in[17];
    float* out = (float*)d_out;

    const size_t smemAC = (128 * 128 + 64 * 128) * sizeof(float);  // 96 KB
    const size_t smemB  = (RMAX_ * H_ + 4 * RMAX_ * 256 + 64 * 256)
                          * sizeof(float);                          // 94 KB
    cudaFuncSetAttribute(kernelA, cudaFuncAttributeMaxDynamicSharedMemorySize,
                         (int)smemAC);
    cudaFuncSetAttribute(kernelB, cudaFuncAttributeMaxDynamicSharedMemorySize,
                         (int)smemB);
    cudaFuncSetAttribute(kernelC, cudaFuncAttributeMaxDynamicSharedMemorySize,
                         (int)smemAC);

    kernelF1<<<62, 256>>>(enc_W, enc_b, enc_mu_W, enc_mu_b, phi_z_W, phi_z_b,
                          dec_W, dec_b, rnn_Wih, phi_x_W, phi_x_b);
    kernelF2<<<90, 256>>>(dec_W, dec_mu_W, dec_mu_b, rnn_Whh, phi_x_W, phi_x_b);
    kernelF3<<<66, 256>>>(rnn_bih, rnn_bhh);
    kernelA<<<dim3(4, T_, C_), 256, smemAC>>>(x);
    kernelB<<<dim3(NB_, C_), 256, smemB>>>(h0);
    kernelC<<<dim3(4, T_, C_), 256, smemAC>>>(out);
}